// round 1
// baseline (speedup 1.0000x reference)
#include <cuda_runtime.h>
#include <cstddef>
#include <cstdint>

// ---------------- problem dims ----------------
constexpr int cB = 8, cS = 1024, cH = 1024, cNH = 16, cHD = 64;
constexpr int cMB = 128, cTOPK = 16, cFF = 4096;
constexpr int cM = cB * cS;   // 8192 rows

// ---------------- scratch (static device globals; no allocs allowed) ----------------
__device__ float g_h1 [(size_t)cM * cH];
__device__ float g_q  [(size_t)cM * cH];
__device__ float g_k  [(size_t)cM * cH];
__device__ float g_v  [(size_t)cM * cH];
__device__ float g_ao [(size_t)cM * cH];
__device__ float g_t1 [(size_t)cM * cH];
__device__ float g_t2 [(size_t)cM * (cH / 4)];
__device__ float g_h  [(size_t)cM * cH];
__device__ float g_h4 [(size_t)cM * cH];
__device__ float g_qkv[(size_t)cM * 3 * cH];
__device__ float g_ff [(size_t)cM * cFF];
__device__ float g_pooled [cB * cH];
__device__ float g_pooled2[cB * cH];
__device__ float g_allocp [cB * cMB];
__device__ float g_retrp  [cB * cMB];
__device__ float g_retrv  [cB * cH];
__device__ float g_sig    [cB * cH];
__device__ int   g_top    [cB * cTOPK];

// ---------------- LayerNorm: one block per row, 256 threads ----------------
__global__ void ln_kernel(const float* __restrict__ x, const float* __restrict__ w,
                          const float* __restrict__ b, float* __restrict__ y) {
    int row = blockIdx.x;
    int t = threadIdx.x;
    float4 v = ((const float4*)(x + (size_t)row * cH))[t];
    float s1 = v.x + v.y + v.z + v.w;
    float s2 = v.x * v.x + v.y * v.y + v.z * v.z + v.w * v.w;
#pragma unroll
    for (int o = 16; o > 0; o >>= 1) {
        s1 += __shfl_xor_sync(0xffffffffu, s1, o);
        s2 += __shfl_xor_sync(0xffffffffu, s2, o);
    }
    __shared__ float sm1[8], sm2[8];
    __shared__ float s_mean, s_rstd;
    if ((t & 31) == 0) { sm1[t >> 5] = s1; sm2[t >> 5] = s2; }
    __syncthreads();
    if (t == 0) {
        float a = 0.f, c = 0.f;
#pragma unroll
        for (int i = 0; i < 8; i++) { a += sm1[i]; c += sm2[i]; }
        float mean = a * (1.0f / cH);
        float var  = c * (1.0f / cH) - mean * mean;
        s_mean = mean;
        s_rstd = rsqrtf(var + 1e-5f);
    }
    __syncthreads();
    float mean = s_mean, rstd = s_rstd;
    float4 wv = ((const float4*)w)[t];
    float4 bv = ((const float4*)b)[t];
    float4 o;
    o.x = (v.x - mean) * rstd * wv.x + bv.x;
    o.y = (v.y - mean) * rstd * wv.y + bv.y;
    o.z = (v.z - mean) * rstd * wv.z + bv.z;
    o.w = (v.w - mean) * rstd * wv.w + bv.w;
    ((float4*)(y + (size_t)row * cH))[t] = o;
}

// ---------------- SGEMM: C[M,N] = act(A[M,K] @ W[N,K]^T + bias) + resid ----------------
// 128x128 tile, BK=8, 256 threads, 8x8 per thread. act: 0 none, 1 relu, 2 gelu(exact).
__global__ void __launch_bounds__(256)
sgemm_kernel(const float* __restrict__ A, int lda,
             const float* __restrict__ W, int ldw,
             float* __restrict__ C, int ldc, int K,
             const float* __restrict__ bias,
             const float* __restrict__ resid, int ldr,
             int act) {
    __shared__ float As[8][128];
    __shared__ float Bs[8][128];
    int tid = threadIdx.x;
    int brow = blockIdx.y * 128, bcol = blockIdx.x * 128;
    int lr = tid >> 1, lc = (tid & 1) * 4;
    const float* Ap = A + (size_t)(brow + lr) * lda + lc;
    const float* Wp = W + (size_t)(bcol + lr) * ldw + lc;
    int tx = tid & 15, ty = tid >> 4;
    float acc[8][8];
#pragma unroll
    for (int i = 0; i < 8; i++)
#pragma unroll
        for (int j = 0; j < 8; j++) acc[i][j] = 0.f;

    for (int k0 = 0; k0 < K; k0 += 8) {
        float4 a4 = *(const float4*)(Ap + k0);
        float4 b4 = *(const float4*)(Wp + k0);
        As[lc + 0][lr] = a4.x; As[lc + 1][lr] = a4.y; As[lc + 2][lr] = a4.z; As[lc + 3][lr] = a4.w;
        Bs[lc + 0][lr] = b4.x; Bs[lc + 1][lr] = b4.y; Bs[lc + 2][lr] = b4.z; Bs[lc + 3][lr] = b4.w;
        __syncthreads();
#pragma unroll
        for (int k = 0; k < 8; k++) {
            float af[8], bf[8];
            *(float4*)(af)     = *(const float4*)&As[k][ty * 8];
            *(float4*)(af + 4) = *(const float4*)&As[k][ty * 8 + 4];
            *(float4*)(bf)     = *(const float4*)&Bs[k][tx * 8];
            *(float4*)(bf + 4) = *(const float4*)&Bs[k][tx * 8 + 4];
#pragma unroll
            for (int i = 0; i < 8; i++)
#pragma unroll
                for (int j = 0; j < 8; j++) acc[i][j] += af[i] * bf[j];
        }
        __syncthreads();
    }
#pragma unroll
    for (int i = 0; i < 8; i++) {
        size_t row = (size_t)(brow + ty * 8 + i);
        float* crow = C + row * (size_t)ldc;
#pragma unroll
        for (int jj = 0; jj < 8; jj += 4) {
            int col = bcol + tx * 8 + jj;
            float4 v;
            v.x = acc[i][jj]; v.y = acc[i][jj + 1]; v.z = acc[i][jj + 2]; v.w = acc[i][jj + 3];
            if (bias) {
                float4 bb = *(const float4*)(bias + col);
                v.x += bb.x; v.y += bb.y; v.z += bb.z; v.w += bb.w;
            }
            if (act == 1) {
                v.x = fmaxf(v.x, 0.f); v.y = fmaxf(v.y, 0.f);
                v.z = fmaxf(v.z, 0.f); v.w = fmaxf(v.w, 0.f);
            } else if (act == 2) {
                const float r2 = 0.70710678118654752f;
                v.x = 0.5f * v.x * (1.f + erff(v.x * r2));
                v.y = 0.5f * v.y * (1.f + erff(v.y * r2));
                v.z = 0.5f * v.z * (1.f + erff(v.z * r2));
                v.w = 0.5f * v.w * (1.f + erff(v.w * r2));
            }
            if (resid) {
                float4 rv = *(const float4*)(resid + row * (size_t)ldr + col);
                v.x += rv.x; v.y += rv.y; v.z += rv.z; v.w += rv.w;
            }
            *(float4*)(crow + col) = v;
        }
    }
}

// ---------------- Flash-style attention: 64-query block, 64-key tiles ----------------
// Heads live in column slices of width 64. grid = (S/64, NH, B), 256 threads.
__global__ void __launch_bounds__(256)
attn_kernel(const float* __restrict__ Q, const float* __restrict__ Km,
            const float* __restrict__ V, int ldi,
            float* __restrict__ O, int ldo) {
    extern __shared__ float sm[];
    float* sQ  = sm;               // [64][64]
    float* sKP = sm + 64 * 64;     // [64][65]  (K tile, then reused for P tile)
    float* sV  = sKP + 64 * 65;    // [64][64]
    int b = blockIdx.z, hh = blockIdx.y;
    int q0 = blockIdx.x * 64;
    size_t hoff = (size_t)b * cS * ldi + hh * cHD;
    const float* Qb = Q + hoff + (size_t)q0 * ldi;
    int tid = threadIdx.x;
    int tx = tid & 15, ty = tid >> 4;

    for (int i = tid; i < 64 * 16; i += 256) {
        int r = i >> 4, c = (i & 15) * 4;
        float4 v4 = *(const float4*)(Qb + (size_t)r * ldi + c);
        float* d = sQ + r * 64 + c;
        d[0] = v4.x * 0.125f; d[1] = v4.y * 0.125f; d[2] = v4.z * 0.125f; d[3] = v4.w * 0.125f;
    }

    float m_[4], l_[4], o_[4][4];
#pragma unroll
    for (int i = 0; i < 4; i++) {
        m_[i] = -1e30f; l_[i] = 0.f;
#pragma unroll
        for (int j = 0; j < 4; j++) o_[i][j] = 0.f;
    }

    for (int kt = 0; kt < cS; kt += 64) {
        const float* Kb = Km + hoff + (size_t)kt * ldi;
        const float* Vb = V  + hoff + (size_t)kt * ldi;
        __syncthreads();   // prev iter consumers of sKP/sV done (also fences first-iter sQ)
        for (int i = tid; i < 64 * 16; i += 256) {
            int r = i >> 4, c = (i & 15) * 4;
            float4 kv = *(const float4*)(Kb + (size_t)r * ldi + c);
            float* dk = sKP + r * 65 + c;
            dk[0] = kv.x; dk[1] = kv.y; dk[2] = kv.z; dk[3] = kv.w;
            float4 vv = *(const float4*)(Vb + (size_t)r * ldi + c);
            float* dv = sV + r * 64 + c;
            dv[0] = vv.x; dv[1] = vv.y; dv[2] = vv.z; dv[3] = vv.w;
        }
        __syncthreads();
        // S = (Q*scale) @ K^T   (4x4 per thread)
        float s_[4][4];
#pragma unroll
        for (int i = 0; i < 4; i++)
#pragma unroll
            for (int j = 0; j < 4; j++) s_[i][j] = 0.f;
        for (int k = 0; k < 64; k++) {
            float a0 = sQ[(ty * 4 + 0) * 64 + k], a1 = sQ[(ty * 4 + 1) * 64 + k];
            float a2 = sQ[(ty * 4 + 2) * 64 + k], a3 = sQ[(ty * 4 + 3) * 64 + k];
            float b0 = sKP[(tx * 4 + 0) * 65 + k], b1 = sKP[(tx * 4 + 1) * 65 + k];
            float b2 = sKP[(tx * 4 + 2) * 65 + k], b3 = sKP[(tx * 4 + 3) * 65 + k];
            s_[0][0] += a0 * b0; s_[0][1] += a0 * b1; s_[0][2] += a0 * b2; s_[0][3] += a0 * b3;
            s_[1][0] += a1 * b0; s_[1][1] += a1 * b1; s_[1][2] += a1 * b2; s_[1][3] += a1 * b3;
            s_[2][0] += a2 * b0; s_[2][1] += a2 * b1; s_[2][2] += a2 * b2; s_[2][3] += a2 * b3;
            s_[3][0] += a3 * b0; s_[3][1] += a3 * b1; s_[3][2] += a3 * b2; s_[3][3] += a3 * b3;
        }
        // online softmax (row stats reduced over the 16 tx lanes)
#pragma unroll
        for (int i = 0; i < 4; i++) {
            float mx = fmaxf(fmaxf(s_[i][0], s_[i][1]), fmaxf(s_[i][2], s_[i][3]));
#pragma unroll
            for (int o = 8; o > 0; o >>= 1) mx = fmaxf(mx, __shfl_xor_sync(0xffffffffu, mx, o));
            float mnew = fmaxf(m_[i], mx);
            float corr = __expf(m_[i] - mnew);
            float rs = 0.f;
#pragma unroll
            for (int j = 0; j < 4; j++) { float p = __expf(s_[i][j] - mnew); s_[i][j] = p; rs += p; }
#pragma unroll
            for (int o = 8; o > 0; o >>= 1) rs += __shfl_xor_sync(0xffffffffu, rs, o);
            l_[i] = l_[i] * corr + rs;
#pragma unroll
            for (int j = 0; j < 4; j++) o_[i][j] *= corr;
            m_[i] = mnew;
        }
        __syncthreads();   // all K-tile readers done before overwriting with P
#pragma unroll
        for (int i = 0; i < 4; i++)
#pragma unroll
            for (int j = 0; j < 4; j++)
                sKP[(ty * 4 + i) * 65 + tx * 4 + j] = s_[i][j];
        __syncthreads();
        // O += P @ V
        for (int k = 0; k < 64; k++) {
            float p0 = sKP[(ty * 4 + 0) * 65 + k], p1 = sKP[(ty * 4 + 1) * 65 + k];
            float p2 = sKP[(ty * 4 + 2) * 65 + k], p3 = sKP[(ty * 4 + 3) * 65 + k];
            float v0 = sV[k * 64 + tx * 4 + 0], v1 = sV[k * 64 + tx * 4 + 1];
            float v2 = sV[k * 64 + tx * 4 + 2], v3 = sV[k * 64 + tx * 4 + 3];
            o_[0][0] += p0 * v0; o_[0][1] += p0 * v1; o_[0][2] += p0 * v2; o_[0][3] += p0 * v3;
            o_[1][0] += p1 * v0; o_[1][1] += p1 * v1; o_[1][2] += p1 * v2; o_[1][3] += p1 * v3;
            o_[2][0] += p2 * v0; o_[2][1] += p2 * v1; o_[2][2] += p2 * v2; o_[2][3] += p2 * v3;
            o_[3][0] += p3 * v0; o_[3][1] += p3 * v1; o_[3][2] += p3 * v2; o_[3][3] += p3 * v3;
        }
    }
    float* Ob = O + ((size_t)(b * cS + q0)) * ldo + hh * cHD;
#pragma unroll
    for (int i = 0; i < 4; i++) {
        int r = ty * 4 + i;
        float inv = 1.f / l_[i];
#pragma unroll
        for (int j = 0; j < 4; j++)
            Ob[(size_t)r * ldo + tx * 4 + j] = o_[i][j] * inv;
    }
}

// ---------------- small kernels ----------------
// if NOT recycling, h <- h1 (recycle branch output otherwise already in h)
__global__ void select_kernel(const float* __restrict__ h1, float* __restrict__ h,
                              const int* __restrict__ li) {
    int L = *li;
    if ((L % 4 == 0) && L > 0) return;
    size_t i = (size_t)blockIdx.x * blockDim.x + threadIdx.x;
    ((float4*)h)[i] = ((const float4*)h1)[i];
}

__global__ void pool_kernel(const float* __restrict__ hbuf, float* __restrict__ pooled) {
    int b = blockIdx.y;
    int col = blockIdx.x * blockDim.x + threadIdx.x;
    const float* p = hbuf + (size_t)b * cS * cH + col;
    float a0 = 0, a1 = 0, a2 = 0, a3 = 0;
    for (int s = 0; s < cS; s += 4) {
        a0 += p[(size_t)s * cH];
        a1 += p[(size_t)(s + 1) * cH];
        a2 += p[(size_t)(s + 2) * cH];
        a3 += p[(size_t)(s + 3) * cH];
    }
    pooled[b * cH + col] = (a0 + a1 + a2 + a3) * (1.0f / cS);
}

// blockIdx.x: 0 -> alloc, 1 -> retr; blockIdx.y = batch; 128 threads = 128 logits
__global__ void allocretr_kernel(const float* __restrict__ pooled,
                                 const float* __restrict__ aw, const float* __restrict__ ab,
                                 const float* __restrict__ rw, const float* __restrict__ rb,
                                 float* __restrict__ alloc_o, float* __restrict__ retr_o) {
    int b = blockIdx.y;
    int which = blockIdx.x;
    const float* w  = which ? rw : aw;
    const float* bi = which ? rb : ab;
    float* out = which ? retr_o : alloc_o;
    int n = threadIdx.x;
    const float* p  = pooled + b * cH;
    const float* wr = w + (size_t)n * cH;
    float acc = bi[n];
    for (int k = 0; k < cH; k += 4)
        acc += p[k] * wr[k] + p[k + 1] * wr[k + 1] + p[k + 2] * wr[k + 2] + p[k + 3] * wr[k + 3];
    __shared__ float red[cMB];
    red[n] = acc; __syncthreads();
    for (int o = 64; o > 0; o >>= 1) { if (n < o) red[n] = fmaxf(red[n], red[n + o]); __syncthreads(); }
    float mx = red[0]; __syncthreads();
    float e = __expf(acc - mx);
    red[n] = e; __syncthreads();
    for (int o = 64; o > 0; o >>= 1) { if (n < o) red[n] += red[n + o]; __syncthreads(); }
    out[b * cMB + n] = e / red[0];
}

__global__ void retrieve_kernel(const float* __restrict__ retr_o,
                                const float* __restrict__ memb, float* __restrict__ retrv) {
    int b = blockIdx.y;
    int col = blockIdx.x * blockDim.x + threadIdx.x;
    float acc = 0.f;
#pragma unroll 4
    for (int r = 0; r < cMB; r++) acc += retr_o[b * cMB + r] * memb[(size_t)r * cH + col];
    retrv[b * cH + col] = acc;
}

__global__ void addmem_kernel(float* __restrict__ h, const float* __restrict__ retrv,
                              const float* __restrict__ msc, const int* __restrict__ li) {
    float sc = msc[*li];
    size_t idx = ((size_t)blockIdx.x * blockDim.x + threadIdx.x) * 4;
    int b = (int)(idx / ((size_t)cS * cH));
    int c = (int)(idx % cH);
    float4 r = *(const float4*)(retrv + b * cH + c);
    float4 v = *(float4*)(h + idx);
    v.x += r.x * sc; v.y += r.y * sc; v.z += r.z * sc; v.w += r.w * sc;
    *(float4*)(h + idx) = v;
}

// pooled2 = pooled + scale*retrieved (mean of broadcast add == add of means)
__global__ void pooled2_kernel(const float* __restrict__ pooled, const float* __restrict__ retrv,
                               const float* __restrict__ msc, const int* __restrict__ li,
                               float* __restrict__ pooled2) {
    float sc = msc[*li];
    int i = blockIdx.x * blockDim.x + threadIdx.x;
    pooled2[i] = pooled[i] + retrv[i] * sc;
}

__global__ void upd_kernel(const float* __restrict__ pooled2, const float* __restrict__ uw,
                           const float* __restrict__ ub, float* __restrict__ sig) {
    int b = blockIdx.y;
    int n = blockIdx.x * blockDim.x + threadIdx.x;
    const float* p = pooled2 + b * cH;
    const float* w = uw + (size_t)n * cH;
    float acc = ub[n];
    for (int k = 0; k < cH; k += 4)
        acc += p[k] * w[k] + p[k + 1] * w[k + 1] + p[k + 2] * w[k + 2] + p[k + 3] * w[k + 3];
    sig[b * cH + n] = 1.f / (1.f + __expf(-acc));
}

__global__ void topk_kernel(const float* __restrict__ alloc_o, int* __restrict__ top) {
    int b = blockIdx.x;
    if (threadIdx.x != 0) return;
    float v[cMB];
    for (int i = 0; i < cMB; i++) v[i] = alloc_o[b * cMB + i];
    for (int k = 0; k < cTOPK; k++) {
        int arg = 0; float best = v[0];
        for (int i = 1; i < cMB; i++) if (v[i] > best) { best = v[i]; arg = i; }
        top[b * cTOPK + k] = arg;
        v[arg] = -1e30f;
    }
}

// row r of new mem bank: last batch whose top-k contains r wins; else original row
__global__ void scatter_kernel(const int* __restrict__ top, const float* __restrict__ sig,
                               const float* __restrict__ memb, float* __restrict__ outm) {
    int r = blockIdx.x;
    __shared__ int sel;
    if (threadIdx.x == 0) {
        int s = -1;
        for (int bb = 0; bb < cB; bb++)
            for (int k = 0; k < cTOPK; k++)
                if (top[bb * cTOPK + k] == r) s = bb;
        sel = s;
    }
    __syncthreads();
    const float* src = (sel >= 0) ? (sig + (size_t)sel * cH) : (memb + (size_t)r * cH);
    for (int c = threadIdx.x; c < cH; c += blockDim.x)
        outm[(size_t)r * cH + c] = src[c];
}

// ---------------- launch ----------------
extern "C" void kernel_launch(void* const* d_in, const int* in_sizes, int n_in,
                              void* d_out, int out_size) {
    (void)in_sizes; (void)n_in; (void)out_size;
    const float* x    = (const float*)d_in[0];
    const float* ln1w = (const float*)d_in[1];
    const float* ln1b = (const float*)d_in[2];
    const float* ln2w = (const float*)d_in[3];
    const float* ln2b = (const float*)d_in[4];
    const float* wq   = (const float*)d_in[5];
    const float* wk   = (const float*)d_in[6];
    const float* wv   = (const float*)d_in[7];
    const float* wo   = (const float*)d_in[8];
    const float* ad1  = (const float*)d_in[9];
    const float* ad2  = (const float*)d_in[10];
    const float* memb = (const float*)d_in[11];
    const float* aw   = (const float*)d_in[12];
    const float* ab   = (const float*)d_in[13];
    const float* rw   = (const float*)d_in[14];
    const float* rb   = (const float*)d_in[15];
    const float* uw   = (const float*)d_in[16];
    const float* ub   = (const float*)d_in[17];
    const float* msc  = (const float*)d_in[18];
    const float* aiw  = (const float*)d_in[19];
    const float* aib  = (const float*)d_in[20];
    const float* aow  = (const float*)d_in[21];
    const float* aob  = (const float*)d_in[22];
    const float* m1w  = (const float*)d_in[23];
    const float* m1b  = (const float*)d_in[24];
    const float* m2w  = (const float*)d_in[25];
    const float* m2b  = (const float*)d_in[26];
    const int*   li   = (const int*)d_in[27];
    float* out  = (float*)d_out;
    float* outm = out + (size_t)cM * cH;

    float *p_h1, *p_q, *p_k, *p_v, *p_ao, *p_t1, *p_t2, *p_h, *p_h4, *p_qkv, *p_ff;
    float *p_pooled, *p_pooled2, *p_alloc, *p_retr, *p_retrv, *p_sig;
    int* p_top;
    cudaGetSymbolAddress((void**)&p_h1, g_h1);
    cudaGetSymbolAddress((void**)&p_q, g_q);
    cudaGetSymbolAddress((void**)&p_k, g_k);
    cudaGetSymbolAddress((void**)&p_v, g_v);
    cudaGetSymbolAddress((void**)&p_ao, g_ao);
    cudaGetSymbolAddress((void**)&p_t1, g_t1);
    cudaGetSymbolAddress((void**)&p_t2, g_t2);
    cudaGetSymbolAddress((void**)&p_h, g_h);
    cudaGetSymbolAddress((void**)&p_h4, g_h4);
    cudaGetSymbolAddress((void**)&p_qkv, g_qkv);
    cudaGetSymbolAddress((void**)&p_ff, g_ff);
    cudaGetSymbolAddress((void**)&p_pooled, g_pooled);
    cudaGetSymbolAddress((void**)&p_pooled2, g_pooled2);
    cudaGetSymbolAddress((void**)&p_alloc, g_allocp);
    cudaGetSymbolAddress((void**)&p_retr, g_retrp);
    cudaGetSymbolAddress((void**)&p_retrv, g_retrv);
    cudaGetSymbolAddress((void**)&p_sig, g_sig);
    cudaGetSymbolAddress((void**)&p_top, g_top);

    const int ASM = (64 * 64 + 64 * 65 + 64 * 64) * 4;   // 49408 B
    cudaFuncSetAttribute(attn_kernel, cudaFuncAttributeMaxDynamicSharedMemorySize, 50176);

    dim3 g1024(8, 64), g256(2, 64), g3072(24, 64), g4096(32, 64);
    dim3 gattn(cS / 64, cNH, cB);

    // h1 = LN1(x)
    ln_kernel<<<cM, 256>>>(x, ln1w, ln1b, p_h1);
    // --- recycle branch (layer_idx=4 -> active; select_kernel handles the other case) ---
    sgemm_kernel<<<g1024, 256>>>(p_h1, cH, wq, cH, p_q, cH, cH, nullptr, nullptr, 0, 0);
    sgemm_kernel<<<g1024, 256>>>(p_h1, cH, wk, cH, p_k, cH, cH, nullptr, nullptr, 0, 0);
    sgemm_kernel<<<g1024, 256>>>(p_h1, cH, wv, cH, p_v, cH, cH, nullptr, nullptr, 0, 0);
    attn_kernel<<<gattn, 256, ASM>>>(p_q, p_k, p_v, cH, p_ao, cH);
    sgemm_kernel<<<g1024, 256>>>(p_ao, cH, wo, cH, p_t1, cH, cH, nullptr, nullptr, 0, 0);
    sgemm_kernel<<<g256,  256>>>(p_t1, cH, ad1, cH, p_t2, cH / 4, cH, nullptr, nullptr, 0, 1);
    sgemm_kernel<<<g1024, 256>>>(p_t2, cH / 4, ad2, cH / 4, p_h, cH, cH / 4, nullptr, nullptr, 0, 0);
    select_kernel<<<cM * cH / 4 / 256, 256>>>(p_h1, p_h, li);
    // --- memory manager ---
    pool_kernel<<<dim3(cH / 256, cB), 256>>>(p_h, p_pooled);
    allocretr_kernel<<<dim3(2, cB), cMB>>>(p_pooled, aw, ab, rw, rb, p_alloc, p_retr);
    retrieve_kernel<<<dim3(cH / 256, cB), 256>>>(p_retr, memb, p_retrv);
    addmem_kernel<<<cM * cH / 4 / 256, 256>>>(p_h, p_retrv, msc, li);
    pooled2_kernel<<<cB * cH / 256, 256>>>(p_pooled, p_retrv, msc, li, p_pooled2);
    upd_kernel<<<dim3(cH / 128, cB), 128>>>(p_pooled2, uw, ub, p_sig);
    topk_kernel<<<cB, 32>>>(p_alloc, p_top);
    scatter_kernel<<<cMB, 256>>>(p_top, p_sig, memb, outm);
    // --- self attention ---
    sgemm_kernel<<<g3072, 256>>>(p_h, cH, aiw, cH, p_qkv, 3 * cH, cH, aib, nullptr, 0, 0);
    attn_kernel<<<gattn, 256, ASM>>>(p_qkv, p_qkv + cH, p_qkv + 2 * cH, 3 * cH, p_ao, cH);
    sgemm_kernel<<<g1024, 256>>>(p_ao, cH, aow, cH, p_h4, cH, cH, aob, x, cH, 0);
    // --- MLP ---
    ln_kernel<<<cM, 256>>>(p_h4, ln2w, ln2b, p_h1);
    sgemm_kernel<<<g4096, 256>>>(p_h1, cH, m1w, cH, p_ff, cFF, cH, m1b, nullptr, 0, 2);
    sgemm_kernel<<<g1024, 256>>>(p_ff, cFF, m2w, cFF, out, cH, cFF, m2b, p_h4, cH, 0);
}

// round 4
// speedup vs baseline: 1.6279x; 1.6279x over previous
#include <cuda_runtime.h>
#include <cuda_bf16.h>
#include <cstddef>
#include <cstdint>

// ---------------- problem dims ----------------
constexpr int cB = 8, cS = 1024, cH = 1024, cNH = 16, cHD = 64;
constexpr int cMB = 128, cTOPK = 16, cFF = 4096;
constexpr int cM = cB * cS;   // 8192 rows

// ---------------- scratch (static device globals; no allocs allowed) ----------------
__device__ float g_h1 [(size_t)cM * cH];
__device__ float g_q  [(size_t)cM * cH];
__device__ float g_k  [(size_t)cM * cH];
__device__ float g_v  [(size_t)cM * cH];
__device__ float g_ao [(size_t)cM * cH];
__device__ float g_t1 [(size_t)cM * cH];
__device__ float g_t2 [(size_t)cM * (cH / 4)];
__device__ float g_h  [(size_t)cM * cH];
__device__ float g_h4 [(size_t)cM * cH];
__device__ float g_qkv[(size_t)cM * 3 * cH];
__device__ float g_ff [(size_t)cM * cFF];
__device__ float g_pooled [cB * cH];
__device__ float g_pooled2[cB * cH];
__device__ float g_allocp [cB * cMB];
__device__ float g_retrp  [cB * cMB];
__device__ float g_retrv  [cB * cH];
__device__ float g_sig    [cB * cH];
__device__ int   g_top    [cB * cTOPK];
// bf16 split buffers
__device__ __nv_bfloat16 g_sA[(size_t)cM * 3 * cH];
__device__ __nv_bfloat16 g_sF[(size_t)cM * 3 * cFF];
__device__ __nv_bfloat16 g_sW[(size_t)cFF * 3 * cH];

// ---------------- helpers ----------------
__device__ __forceinline__ uint32_t smem_u32(const void* p) {
    uint32_t a;
    asm("{ .reg .u64 t; cvta.to.shared.u64 t, %1; cvt.u32.u64 %0, t; }" : "=r"(a) : "l"(p));
    return a;
}
#define CP16(dst, src) \
    asm volatile("cp.async.cg.shared.global [%0], [%1], 16;" :: "r"(dst), "l"(src))
#define CP_COMMIT() asm volatile("cp.async.commit_group;" ::: "memory")
#define CP_WAIT1() asm volatile("cp.async.wait_group 1;" ::: "memory")

__device__ __forceinline__ void ldmx4(uint32_t* r, uint32_t addr) {
    asm volatile("ldmatrix.sync.aligned.m8n8.x4.shared.b16 {%0,%1,%2,%3}, [%4];"
                 : "=r"(r[0]), "=r"(r[1]), "=r"(r[2]), "=r"(r[3]) : "r"(addr));
}
__device__ __forceinline__ void mma16816(float* c, const uint32_t* a, uint32_t b0, uint32_t b1) {
    asm volatile(
        "mma.sync.aligned.m16n8k16.row.col.f32.bf16.bf16.f32 "
        "{%0,%1,%2,%3}, {%4,%5,%6,%7}, {%8,%9}, {%0,%1,%2,%3};"
        : "+f"(c[0]), "+f"(c[1]), "+f"(c[2]), "+f"(c[3])
        : "r"(a[0]), "r"(a[1]), "r"(a[2]), "r"(a[3]), "r"(b0), "r"(b1));
}

// ---------------- split: fp32 -> bf16 [hi|hi|lo] (act) or [hi|lo|hi] (weight) ----------------
__global__ void split_kernel(const float* __restrict__ X, __nv_bfloat16* __restrict__ Y,
                             int K, int wmode) {
    size_t i = (size_t)blockIdx.x * blockDim.x + threadIdx.x;
    int K4 = K >> 2;
    size_t row = i / K4;
    int c4 = (int)(i - row * K4);
    float4 v = ((const float4*)X)[i];
    __nv_bfloat162 h0 = __floats2bfloat162_rn(v.x, v.y);
    __nv_bfloat162 h1 = __floats2bfloat162_rn(v.z, v.w);
    float2 hf0 = __bfloat1622float2(h0), hf1 = __bfloat1622float2(h1);
    __nv_bfloat162 l0 = __floats2bfloat162_rn(v.x - hf0.x, v.y - hf0.y);
    __nv_bfloat162 l1 = __floats2bfloat162_rn(v.z - hf1.x, v.w - hf1.y);
    uint2 Hh, Ll;
    Hh.x = reinterpret_cast<uint32_t&>(h0); Hh.y = reinterpret_cast<uint32_t&>(h1);
    Ll.x = reinterpret_cast<uint32_t&>(l0); Ll.y = reinterpret_cast<uint32_t&>(l1);
    __nv_bfloat16* yr = Y + row * (size_t)(3 * K) + c4 * 4;
    *(uint2*)yr = Hh;
    *(uint2*)(yr + K)     = wmode ? Ll : Hh;
    *(uint2*)(yr + 2 * K) = wmode ? Hh : Ll;
}

// ---------------- HMMA GEMM: C[M,N] = act(A'[M,Kp] @ W'[N,Kp]^T + bias) + resid ----------------
// 128x128x32 tile, 256 threads (warps 4x2), 3-stage cp.async, padded smem (row=40 bf16).
constexpr int GBM = 128, GBN = 128, GBK = 32, GSTAGES = 3;
constexpr int GROW = GBK + 8;                         // 40 bf16 = 80 B row stride
constexpr int GSTG_B = 2 * GBM * GROW * 2;            // 20480 B per stage (A + B)
constexpr int GAB_B = GBM * GROW * 2;                 // 10240 B (A part)

__global__ void __launch_bounds__(256)
mma_gemm_kernel(const __nv_bfloat16* __restrict__ A, const __nv_bfloat16* __restrict__ W,
                int Kp, float* __restrict__ C, int ldc,
                const float* __restrict__ bias,
                const float* __restrict__ resid, int ldr, int act) {
    extern __shared__ __align__(16) char smem[];
    uint32_t sb = smem_u32(smem);
    int tid = threadIdx.x;
    int lane = tid & 31, warp = tid >> 5;
    int wm = warp & 3, wn = warp >> 2;          // 4 x 2 warp grid
    int brow = blockIdx.y * GBM, bcol = blockIdx.x * GBN;

    const char* gA = (const char*)(A + (size_t)brow * Kp);
    const char* gB = (const char*)(W + (size_t)bcol * Kp);

    // per-thread load mapping: 2 x 16B chunks from A and from B
    int r0 = tid >> 2;
    int ch0 = tid & 3;
    int r1 = (tid + 256) >> 2;
    int ch1 = ch0;

    auto load_stage = [&](int s, int kt) {
        uint32_t base = sb + s * GSTG_B;
        size_t gk = (size_t)kt * GBK * 2;   // byte offset along K
        CP16(base + r0 * 80 + ch0 * 16,          gA + (size_t)r0 * Kp * 2 + gk + ch0 * 16);
        CP16(base + r1 * 80 + ch1 * 16,          gA + (size_t)r1 * Kp * 2 + gk + ch1 * 16);
        CP16(base + GAB_B + r0 * 80 + ch0 * 16,  gB + (size_t)r0 * Kp * 2 + gk + ch0 * 16);
        CP16(base + GAB_B + r1 * 80 + ch1 * 16,  gB + (size_t)r1 * Kp * 2 + gk + ch1 * 16);
        CP_COMMIT();
    };

    const int KT = Kp / GBK;
    load_stage(0, 0);
    load_stage(1, 1);

    float acc[2][8][4];
#pragma unroll
    for (int i = 0; i < 2; i++)
#pragma unroll
        for (int j = 0; j < 8; j++)
#pragma unroll
            for (int q = 0; q < 4; q++) acc[i][j][q] = 0.f;

    // ldmatrix lane addressing (constant per thread)
    int a_r = (lane & 15);
    int a_c = (lane >> 4) * 8;
    int b_r = (lane & 7) + ((lane & 16) ? 8 : 0);
    int b_c = ((lane & 8) ? 8 : 0);

    for (int kt = 0; kt < KT; kt++) {
        CP_WAIT1();
        __syncthreads();
        if (kt + 2 < KT) load_stage((kt + 2) % GSTAGES, kt + 2);
        uint32_t abase = sb + (kt % GSTAGES) * GSTG_B;
        uint32_t bbase = abase + GAB_B;
#pragma unroll
        for (int ks = 0; ks < 2; ks++) {
            uint32_t af[2][4], bf[4][4];
#pragma unroll
            for (int mi = 0; mi < 2; mi++) {
                int row = wm * 32 + mi * 16 + a_r;
                int col = ks * 16 + a_c;
                ldmx4(af[mi], abase + row * 80 + col * 2);
            }
#pragma unroll
            for (int nj = 0; nj < 4; nj++) {
                int row = wn * 64 + nj * 16 + b_r;
                int col = ks * 16 + b_c;
                ldmx4(bf[nj], bbase + row * 80 + col * 2);
            }
#pragma unroll
            for (int mi = 0; mi < 2; mi++)
#pragma unroll
                for (int nj = 0; nj < 4; nj++) {
                    mma16816(acc[mi][2 * nj],     af[mi], bf[nj][0], bf[nj][1]);
                    mma16816(acc[mi][2 * nj + 1], af[mi], bf[nj][2], bf[nj][3]);
                }
        }
        __syncthreads();
    }

    // epilogue
    int g = lane >> 2, qc = (lane & 3) * 2;
#pragma unroll
    for (int mi = 0; mi < 2; mi++) {
#pragma unroll
        for (int half = 0; half < 2; half++) {
            size_t row = (size_t)brow + wm * 32 + mi * 16 + g + half * 8;
            float* crow = C + row * (size_t)ldc;
            const float* rrow = resid ? resid + row * (size_t)ldr : nullptr;
#pragma unroll
            for (int n8 = 0; n8 < 8; n8++) {
                int col = bcol + wn * 64 + n8 * 8 + qc;
                float v0 = acc[mi][n8][half * 2 + 0];
                float v1 = acc[mi][n8][half * 2 + 1];
                if (bias) {
                    float2 bb = *(const float2*)(bias + col);
                    v0 += bb.x; v1 += bb.y;
                }
                if (act == 1) {
                    v0 = fmaxf(v0, 0.f); v1 = fmaxf(v1, 0.f);
                } else if (act == 2) {
                    const float r2 = 0.70710678118654752f;
                    v0 = 0.5f * v0 * (1.f + erff(v0 * r2));
                    v1 = 0.5f * v1 * (1.f + erff(v1 * r2));
                }
                if (rrow) {
                    float2 rv = *(const float2*)(rrow + col);
                    v0 += rv.x; v1 += rv.y;
                }
                float2 o; o.x = v0; o.y = v1;
                *(float2*)(crow + col) = o;
            }
        }
    }
}

// ---------------- LayerNorm ----------------
__global__ void ln_kernel(const float* __restrict__ x, const float* __restrict__ w,
                          const float* __restrict__ b, float* __restrict__ y) {
    int row = blockIdx.x;
    int t = threadIdx.x;
    float4 v = ((const float4*)(x + (size_t)row * cH))[t];
    float s1 = v.x + v.y + v.z + v.w;
    float s2 = v.x * v.x + v.y * v.y + v.z * v.z + v.w * v.w;
#pragma unroll
    for (int o = 16; o > 0; o >>= 1) {
        s1 += __shfl_xor_sync(0xffffffffu, s1, o);
        s2 += __shfl_xor_sync(0xffffffffu, s2, o);
    }
    __shared__ float sm1[8], sm2[8];
    __shared__ float s_mean, s_rstd;
    if ((t & 31) == 0) { sm1[t >> 5] = s1; sm2[t >> 5] = s2; }
    __syncthreads();
    if (t == 0) {
        float a = 0.f, c = 0.f;
#pragma unroll
        for (int i = 0; i < 8; i++) { a += sm1[i]; c += sm2[i]; }
        float mean = a * (1.0f / cH);
        float var  = c * (1.0f / cH) - mean * mean;
        s_mean = mean;
        s_rstd = rsqrtf(var + 1e-5f);
    }
    __syncthreads();
    float mean = s_mean, rstd = s_rstd;
    float4 wv = ((const float4*)w)[t];
    float4 bv = ((const float4*)b)[t];
    float4 o;
    o.x = (v.x - mean) * rstd * wv.x + bv.x;
    o.y = (v.y - mean) * rstd * wv.y + bv.y;
    o.z = (v.z - mean) * rstd * wv.z + bv.z;
    o.w = (v.w - mean) * rstd * wv.w + bv.w;
    ((float4*)(y + (size_t)row * cH))[t] = o;
}

// ---------------- Flash-style attention (fp32) ----------------
__global__ void __launch_bounds__(256)
attn_kernel(const float* __restrict__ Q, const float* __restrict__ Km,
            const float* __restrict__ V, int ldi,
            float* __restrict__ O, int ldo) {
    extern __shared__ float sm[];
    float* sQ  = sm;
    float* sKP = sm + 64 * 64;
    float* sV  = sKP + 64 * 65;
    int b = blockIdx.z, hh = blockIdx.y;
    int q0 = blockIdx.x * 64;
    size_t hoff = (size_t)b * cS * ldi + hh * cHD;
    const float* Qb = Q + hoff + (size_t)q0 * ldi;
    int tid = threadIdx.x;
    int tx = tid & 15, ty = tid >> 4;

    for (int i = tid; i < 64 * 16; i += 256) {
        int r = i >> 4, c = (i & 15) * 4;
        float4 v4 = *(const float4*)(Qb + (size_t)r * ldi + c);
        float* d = sQ + r * 64 + c;
        d[0] = v4.x * 0.125f; d[1] = v4.y * 0.125f; d[2] = v4.z * 0.125f; d[3] = v4.w * 0.125f;
    }

    float m_[4], l_[4], o_[4][4];
#pragma unroll
    for (int i = 0; i < 4; i++) {
        m_[i] = -1e30f; l_[i] = 0.f;
#pragma unroll
        for (int j = 0; j < 4; j++) o_[i][j] = 0.f;
    }

    for (int kt = 0; kt < cS; kt += 64) {
        const float* Kb = Km + hoff + (size_t)kt * ldi;
        const float* Vb = V  + hoff + (size_t)kt * ldi;
        __syncthreads();
        for (int i = tid; i < 64 * 16; i += 256) {
            int r = i >> 4, c = (i & 15) * 4;
            float4 kv = *(const float4*)(Kb + (size_t)r * ldi + c);
            float* dk = sKP + r * 65 + c;
            dk[0] = kv.x; dk[1] = kv.y; dk[2] = kv.z; dk[3] = kv.w;
            float4 vv = *(const float4*)(Vb + (size_t)r * ldi + c);
            float* dv = sV + r * 64 + c;
            dv[0] = vv.x; dv[1] = vv.y; dv[2] = vv.z; dv[3] = vv.w;
        }
        __syncthreads();
        float s_[4][4];
#pragma unroll
        for (int i = 0; i < 4; i++)
#pragma unroll
            for (int j = 0; j < 4; j++) s_[i][j] = 0.f;
        for (int k = 0; k < 64; k++) {
            float a0 = sQ[(ty * 4 + 0) * 64 + k], a1 = sQ[(ty * 4 + 1) * 64 + k];
            float a2 = sQ[(ty * 4 + 2) * 64 + k], a3 = sQ[(ty * 4 + 3) * 64 + k];
            float b0 = sKP[(tx * 4 + 0) * 65 + k], b1 = sKP[(tx * 4 + 1) * 65 + k];
            float b2 = sKP[(tx * 4 + 2) * 65 + k], b3 = sKP[(tx * 4 + 3) * 65 + k];
            s_[0][0] += a0 * b0; s_[0][1] += a0 * b1; s_[0][2] += a0 * b2; s_[0][3] += a0 * b3;
            s_[1][0] += a1 * b0; s_[1][1] += a1 * b1; s_[1][2] += a1 * b2; s_[1][3] += a1 * b3;
            s_[2][0] += a2 * b0; s_[2][1] += a2 * b1; s_[2][2] += a2 * b2; s_[2][3] += a2 * b3;
            s_[3][0] += a3 * b0; s_[3][1] += a3 * b1; s_[3][2] += a3 * b2; s_[3][3] += a3 * b3;
        }
#pragma unroll
        for (int i = 0; i < 4; i++) {
            float mx = fmaxf(fmaxf(s_[i][0], s_[i][1]), fmaxf(s_[i][2], s_[i][3]));
#pragma unroll
            for (int o = 8; o > 0; o >>= 1) mx = fmaxf(mx, __shfl_xor_sync(0xffffffffu, mx, o));
            float mnew = fmaxf(m_[i], mx);
            float corr = __expf(m_[i] - mnew);
            float rs = 0.f;
#pragma unroll
            for (int j = 0; j < 4; j++) { float p = __expf(s_[i][j] - mnew); s_[i][j] = p; rs += p; }
#pragma unroll
            for (int o = 8; o > 0; o >>= 1) rs += __shfl_xor_sync(0xffffffffu, rs, o);
            l_[i] = l_[i] * corr + rs;
#pragma unroll
            for (int j = 0; j < 4; j++) o_[i][j] *= corr;
            m_[i] = mnew;
        }
        __syncthreads();
#pragma unroll
        for (int i = 0; i < 4; i++)
#pragma unroll
            for (int j = 0; j < 4; j++)
                sKP[(ty * 4 + i) * 65 + tx * 4 + j] = s_[i][j];
        __syncthreads();
        for (int k = 0; k < 64; k++) {
            float p0 = sKP[(ty * 4 + 0) * 65 + k], p1 = sKP[(ty * 4 + 1) * 65 + k];
            float p2 = sKP[(ty * 4 + 2) * 65 + k], p3 = sKP[(ty * 4 + 3) * 65 + k];
            float v0 = sV[k * 64 + tx * 4 + 0], v1 = sV[k * 64 + tx * 4 + 1];
            float v2 = sV[k * 64 + tx * 4 + 2], v3 = sV[k * 64 + tx * 4 + 3];
            o_[0][0] += p0 * v0; o_[0][1] += p0 * v1; o_[0][2] += p0 * v2; o_[0][3] += p0 * v3;
            o_[1][0] += p1 * v0; o_[1][1] += p1 * v1; o_[1][2] += p1 * v2; o_[1][3] += p1 * v3;
            o_[2][0] += p2 * v0; o_[2][1] += p2 * v1; o_[2][2] += p2 * v2; o_[2][3] += p2 * v3;
            o_[3][0] += p3 * v0; o_[3][1] += p3 * v1; o_[3][2] += p3 * v2; o_[3][3] += p3 * v3;
        }
    }
    float* Ob = O + ((size_t)(b * cS + q0)) * ldo + hh * cHD;
#pragma unroll
    for (int i = 0; i < 4; i++) {
        int r = ty * 4 + i;
        float inv = 1.f / l_[i];
#pragma unroll
        for (int j = 0; j < 4; j++)
            Ob[(size_t)r * ldo + tx * 4 + j] = o_[i][j] * inv;
    }
}

// ---------------- small kernels ----------------
__global__ void select_kernel(const float* __restrict__ h1, float* __restrict__ h,
                              const int* __restrict__ li) {
    int L = *li;
    if ((L % 4 == 0) && L > 0) return;
    size_t i = (size_t)blockIdx.x * blockDim.x + threadIdx.x;
    ((float4*)h)[i] = ((const float4*)h1)[i];
}

__global__ void pool_kernel(const float* __restrict__ hbuf, float* __restrict__ pooled) {
    int b = blockIdx.y;
    int col = blockIdx.x * blockDim.x + threadIdx.x;
    const float* p = hbuf + (size_t)b * cS * cH + col;
    float a0 = 0, a1 = 0, a2 = 0, a3 = 0;
    for (int s = 0; s < cS; s += 4) {
        a0 += p[(size_t)s * cH];
        a1 += p[(size_t)(s + 1) * cH];
        a2 += p[(size_t)(s + 2) * cH];
        a3 += p[(size_t)(s + 3) * cH];
    }
    pooled[b * cH + col] = (a0 + a1 + a2 + a3) * (1.0f / cS);
}

__global__ void allocretr_kernel(const float* __restrict__ pooled,
                                 const float* __restrict__ aw, const float* __restrict__ ab,
                                 const float* __restrict__ rw, const float* __restrict__ rb,
                                 float* __restrict__ alloc_o, float* __restrict__ retr_o) {
    int b = blockIdx.y;
    int which = blockIdx.x;
    const float* w  = which ? rw : aw;
    const float* bi = which ? rb : ab;
    float* out = which ? retr_o : alloc_o;
    int n = threadIdx.x;
    const float* p  = pooled + b * cH;
    const float* wr = w + (size_t)n * cH;
    float acc = bi[n];
    for (int k = 0; k < cH; k += 4)
        acc += p[k] * wr[k] + p[k + 1] * wr[k + 1] + p[k + 2] * wr[k + 2] + p[k + 3] * wr[k + 3];
    __shared__ float red[cMB];
    red[n] = acc; __syncthreads();
    for (int o = 64; o > 0; o >>= 1) { if (n < o) red[n] = fmaxf(red[n], red[n + o]); __syncthreads(); }
    float mx = red[0]; __syncthreads();
    float e = __expf(acc - mx);
    red[n] = e; __syncthreads();
    for (int o = 64; o > 0; o >>= 1) { if (n < o) red[n] += red[n + o]; __syncthreads(); }
    out[b * cMB + n] = e / red[0];
}

__global__ void retrieve_kernel(const float* __restrict__ retr_o,
                                const float* __restrict__ memb, float* __restrict__ retrv) {
    int b = blockIdx.y;
    int col = blockIdx.x * blockDim.x + threadIdx.x;
    float acc = 0.f;
#pragma unroll 4
    for (int r = 0; r < cMB; r++) acc += retr_o[b * cMB + r] * memb[(size_t)r * cH + col];
    retrv[b * cH + col] = acc;
}

__global__ void addmem_kernel(float* __restrict__ h, const float* __restrict__ retrv,
                              const float* __restrict__ msc, const int* __restrict__ li) {
    float sc = msc[*li];
    size_t idx = ((size_t)blockIdx.x * blockDim.x + threadIdx.x) * 4;
    int b = (int)(idx / ((size_t)cS * cH));
    int c = (int)(idx % cH);
    float4 r = *(const float4*)(retrv + b * cH + c);
    float4 v = *(float4*)(h + idx);
    v.x += r.x * sc; v.y += r.y * sc; v.z += r.z * sc; v.w += r.w * sc;
    *(float4*)(h + idx) = v;
}

__global__ void pooled2_kernel(const float* __restrict__ pooled, const float* __restrict__ retrv,
                               const float* __restrict__ msc, const int* __restrict__ li,
                               float* __restrict__ pooled2) {
    float sc = msc[*li];
    int i = blockIdx.x * blockDim.x + threadIdx.x;
    pooled2[i] = pooled[i] + retrv[i] * sc;
}

__global__ void upd_kernel(const float* __restrict__ pooled2, const float* __restrict__ uw,
                           const float* __restrict__ ub, float* __restrict__ sig) {
    int b = blockIdx.y;
    int n = blockIdx.x * blockDim.x + threadIdx.x;
    const float* p = pooled2 + b * cH;
    const float* w = uw + (size_t)n * cH;
    float acc = ub[n];
    for (int k = 0; k < cH; k += 4)
        acc += p[k] * w[k] + p[k + 1] * w[k + 1] + p[k + 2] * w[k + 2] + p[k + 3] * w[k + 3];
    sig[b * cH + n] = 1.f / (1.f + __expf(-acc));
}

__global__ void topk_kernel(const float* __restrict__ alloc_o, int* __restrict__ top) {
    int b = blockIdx.x;
    if (threadIdx.x != 0) return;
    float v[cMB];
    for (int i = 0; i < cMB; i++) v[i] = alloc_o[b * cMB + i];
    for (int k = 0; k < cTOPK; k++) {
        int arg = 0; float best = v[0];
        for (int i = 1; i < cMB; i++) if (v[i] > best) { best = v[i]; arg = i; }
        top[b * cTOPK + k] = arg;
        v[arg] = -1e30f;
    }
}

__global__ void scatter_kernel(const int* __restrict__ top, const float* __restrict__ sig,
                               const float* __restrict__ memb, float* __restrict__ outm) {
    int r = blockIdx.x;
    __shared__ int sel;
    if (threadIdx.x == 0) {
        int s = -1;
        for (int bb = 0; bb < cB; bb++)
            for (int k = 0; k < cTOPK; k++)
                if (top[bb * cTOPK + k] == r) s = bb;
        sel = s;
    }
    __syncthreads();
    const float* src = (sel >= 0) ? (sig + (size_t)sel * cH) : (memb + (size_t)r * cH);
    for (int c = threadIdx.x; c < cH; c += blockDim.x)
        outm[(size_t)r * cH + c] = src[c];
}

// ---------------- launch ----------------
extern "C" void kernel_launch(void* const* d_in, const int* in_sizes, int n_in,
                              void* d_out, int out_size) {
    (void)in_sizes; (void)n_in; (void)out_size;
    const float* x    = (const float*)d_in[0];
    const float* ln1w = (const float*)d_in[1];
    const float* ln1b = (const float*)d_in[2];
    const float* ln2w = (const float*)d_in[3];
    const float* ln2b = (const float*)d_in[4];
    const float* wq   = (const float*)d_in[5];
    const float* wk   = (const float*)d_in[6];
    const float* wv   = (const float*)d_in[7];
    const float* wo   = (const float*)d_in[8];
    const float* ad1  = (const float*)d_in[9];
    const float* ad2  = (const float*)d_in[10];
    const float* memb = (const float*)d_in[11];
    const float* aw   = (const float*)d_in[12];
    const float* ab   = (const float*)d_in[13];
    const float* rw   = (const float*)d_in[14];
    const float* rb   = (const float*)d_in[15];
    const float* uw   = (const float*)d_in[16];
    const float* ub   = (const float*)d_in[17];
    const float* msc  = (const float*)d_in[18];
    const float* aiw  = (const float*)d_in[19];
    const float* aib  = (const float*)d_in[20];
    const float* aow  = (const float*)d_in[21];
    const float* aob  = (const float*)d_in[22];
    const float* m1w  = (const float*)d_in[23];
    const float* m1b  = (const float*)d_in[24];
    const float* m2w  = (const float*)d_in[25];
    const float* m2b  = (const float*)d_in[26];
    const int*   li   = (const int*)d_in[27];
    float* out  = (float*)d_out;
    float* outm = out + (size_t)cM * cH;

    float *p_h1, *p_q, *p_k, *p_v, *p_ao, *p_t1, *p_t2, *p_h, *p_h4, *p_qkv, *p_ff;
    float *p_pooled, *p_pooled2, *p_alloc, *p_retr, *p_retrv, *p_sig;
    int* p_top;
    __nv_bfloat16 *p_sA, *p_sF, *p_sW;
    cudaGetSymbolAddress((void**)&p_h1, g_h1);
    cudaGetSymbolAddress((void**)&p_q, g_q);
    cudaGetSymbolAddress((void**)&p_k, g_k);
    cudaGetSymbolAddress((void**)&p_v, g_v);
    cudaGetSymbolAddress((void**)&p_ao, g_ao);
    cudaGetSymbolAddress((void**)&p_t1, g_t1);
    cudaGetSymbolAddress((void**)&p_t2, g_t2);
    cudaGetSymbolAddress((void**)&p_h, g_h);
    cudaGetSymbolAddress((void**)&p_h4, g_h4);
    cudaGetSymbolAddress((void**)&p_qkv, g_qkv);
    cudaGetSymbolAddress((void**)&p_ff, g_ff);
    cudaGetSymbolAddress((void**)&p_pooled, g_pooled);
    cudaGetSymbolAddress((void**)&p_pooled2, g_pooled2);
    cudaGetSymbolAddress((void**)&p_alloc, g_allocp);
    cudaGetSymbolAddress((void**)&p_retr, g_retrp);
    cudaGetSymbolAddress((void**)&p_retrv, g_retrv);
    cudaGetSymbolAddress((void**)&p_sig, g_sig);
    cudaGetSymbolAddress((void**)&p_top, g_top);
    cudaGetSymbolAddress((void**)&p_sA, g_sA);
    cudaGetSymbolAddress((void**)&p_sF, g_sF);
    cudaGetSymbolAddress((void**)&p_sW, g_sW);

    const int ASM = (64 * 64 + 64 * 65 + 64 * 64) * 4;
    cudaFuncSetAttribute(attn_kernel, cudaFuncAttributeMaxDynamicSharedMemorySize, 50176);
    const int GSM = GSTAGES * GSTG_B;   // 61440
    cudaFuncSetAttribute(mma_gemm_kernel, cudaFuncAttributeMaxDynamicSharedMemorySize, GSM);

    dim3 gattn(cS / 64, cNH, cB);
    auto splitA = [&](const float* src, __nv_bfloat16* dst, int K) {
        split_kernel<<<(int)(((size_t)cM * K / 4) / 256), 256>>>(src, dst, K, 0);
    };
    auto splitW = [&](const float* src, int N, int K) {
        split_kernel<<<(int)(((size_t)N * K / 4) / 256), 256>>>(src, p_sW, K, 1);
    };

    // h1 = LN1(x)
    ln_kernel<<<cM, 256>>>(x, ln1w, ln1b, p_h1);
    // --- recycle branch (active for layer_idx=4; select_kernel fixes the other case) ---
    splitA(p_h1, p_sA, cH);
    splitW(wq, cH, cH);
    mma_gemm_kernel<<<dim3(8, 64), 256, GSM>>>(p_sA, p_sW, 3072, p_q, cH, nullptr, nullptr, 0, 0);
    splitW(wk, cH, cH);
    mma_gemm_kernel<<<dim3(8, 64), 256, GSM>>>(p_sA, p_sW, 3072, p_k, cH, nullptr, nullptr, 0, 0);
    splitW(wv, cH, cH);
    mma_gemm_kernel<<<dim3(8, 64), 256, GSM>>>(p_sA, p_sW, 3072, p_v, cH, nullptr, nullptr, 0, 0);
    attn_kernel<<<gattn, 256, ASM>>>(p_q, p_k, p_v, cH, p_ao, cH);
    splitA(p_ao, p_sA, cH);
    splitW(wo, cH, cH);
    mma_gemm_kernel<<<dim3(8, 64), 256, GSM>>>(p_sA, p_sW, 3072, p_t1, cH, nullptr, nullptr, 0, 0);
    splitA(p_t1, p_sA, cH);
    splitW(ad1, cH / 4, cH);
    mma_gemm_kernel<<<dim3(2, 64), 256, GSM>>>(p_sA, p_sW, 3072, p_t2, cH / 4, nullptr, nullptr, 0, 1);
    splitA(p_t2, p_sA, cH / 4);
    splitW(ad2, cH, cH / 4);
    mma_gemm_kernel<<<dim3(8, 64), 256, GSM>>>(p_sA, p_sW, 768, p_h, cH, nullptr, nullptr, 0, 0);
    select_kernel<<<cM * cH / 4 / 256, 256>>>(p_h1, p_h, li);
    // --- memory manager ---
    pool_kernel<<<dim3(cH / 256, cB), 256>>>(p_h, p_pooled);
    allocretr_kernel<<<dim3(2, cB), cMB>>>(p_pooled, aw, ab, rw, rb, p_alloc, p_retr);
    retrieve_kernel<<<dim3(cH / 256, cB), 256>>>(p_retr, memb, p_retrv);
    addmem_kernel<<<cM * cH / 4 / 256, 256>>>(p_h, p_retrv, msc, li);
    pooled2_kernel<<<cB * cH / 256, 256>>>(p_pooled, p_retrv, msc, li, p_pooled2);
    upd_kernel<<<dim3(cH / 128, cB), 128>>>(p_pooled2, uw, ub, p_sig);
    topk_kernel<<<cB, 32>>>(p_alloc, p_top);
    scatter_kernel<<<cMB, 256>>>(p_top, p_sig, memb, outm);
    // --- self attention ---
    splitA(p_h, p_sA, cH);
    splitW(aiw, 3 * cH, cH);
    mma_gemm_kernel<<<dim3(24, 64), 256, GSM>>>(p_sA, p_sW, 3072, p_qkv, 3 * cH, aib, nullptr, 0, 0);
    attn_kernel<<<gattn, 256, ASM>>>(p_qkv, p_qkv + cH, p_qkv + 2 * cH, 3 * cH, p_ao, cH);
    splitA(p_ao, p_sA, cH);
    splitW(aow, cH, cH);
    mma_gemm_kernel<<<dim3(8, 64), 256, GSM>>>(p_sA, p_sW, 3072, p_h4, cH, aob, x, cH, 0);
    // --- MLP ---
    ln_kernel<<<cM, 256>>>(p_h4, ln2w, ln2b, p_h1);
    splitA(p_h1, p_sA, cH);
    splitW(m1w, cFF, cH);
    mma_gemm_kernel<<<dim3(32, 64), 256, GSM>>>(p_sA, p_sW, 3072, p_ff, cFF, m1b, nullptr, 0, 2);
    splitA(p_ff, p_sF, cFF);
    splitW(m2w, cH, cFF);
    mma_gemm_kernel<<<dim3(8, 64), 256, GSM>>>(p_sF, p_sW, 12288, out, cH, m2b, p_h4, cH, 0);
}

// round 7
// speedup vs baseline: 2.0773x; 1.2761x over previous
#include <cuda_runtime.h>
#include <cuda_bf16.h>
#include <cstddef>
#include <cstdint>

constexpr int cB = 8, cS = 1024, cH = 1024, cNH = 16, cHD = 64;
constexpr int cMB = 128, cTOPK = 16, cFF = 4096;
constexpr int cM = cB * cS;

// ---------------- scratch ----------------
__device__ float g_h1 [(size_t)cM * cH];
__device__ float g_ao [(size_t)cM * cH];
__device__ float g_t1 [(size_t)cM * cH];
__device__ float g_t2 [(size_t)cM * (cH / 4)];
__device__ float g_h  [(size_t)cM * cH];
__device__ float g_h4 [(size_t)cM * cH];
__device__ float g_qkv[(size_t)cM * 3 * cH];
__device__ float g_ff [(size_t)cM * cFF];
__device__ float g_pooled [cB * cH];
__device__ float g_pooled2[cB * cH];
__device__ float g_allocp [cB * cMB];
__device__ float g_retrp  [cB * cMB];
__device__ float g_retrv  [cB * cH];
__device__ float g_sig    [cB * cH];
__device__ int   g_top    [cB * cTOPK];
__device__ __nv_bfloat16 g_sA[(size_t)cM * 3 * cH];
__device__ __nv_bfloat16 g_sF[(size_t)cM * 3 * cFF];
__device__ __nv_bfloat16 g_sW[(size_t)cFF * 3 * cH];

// ---------------- helpers ----------------
__device__ __forceinline__ uint32_t smem_u32(const void* p) {
    uint32_t a;
    asm("{ .reg .u64 t; cvta.to.shared.u64 t, %1; cvt.u32.u64 %0, t; }" : "=r"(a) : "l"(p));
    return a;
}
#define CP16(dst, src) \
    asm volatile("cp.async.cg.shared.global [%0], [%1], 16;" :: "r"(dst), "l"(src))
#define CP_COMMIT() asm volatile("cp.async.commit_group;" ::: "memory")
#define CP_WAIT1() asm volatile("cp.async.wait_group 1;" ::: "memory")

__device__ __forceinline__ void ldmx4(uint32_t* r, uint32_t addr) {
    asm volatile("ldmatrix.sync.aligned.m8n8.x4.shared.b16 {%0,%1,%2,%3}, [%4];"
                 : "=r"(r[0]), "=r"(r[1]), "=r"(r[2]), "=r"(r[3]) : "r"(addr));
}
__device__ __forceinline__ void ldmx4t(uint32_t* r, uint32_t addr) {
    asm volatile("ldmatrix.sync.aligned.m8n8.x4.trans.shared.b16 {%0,%1,%2,%3}, [%4];"
                 : "=r"(r[0]), "=r"(r[1]), "=r"(r[2]), "=r"(r[3]) : "r"(addr));
}
__device__ __forceinline__ void mma16816(float* c, const uint32_t* a, uint32_t b0, uint32_t b1) {
    asm volatile(
        "mma.sync.aligned.m16n8k16.row.col.f32.bf16.bf16.f32 "
        "{%0,%1,%2,%3}, {%4,%5,%6,%7}, {%8,%9}, {%0,%1,%2,%3};"
        : "+f"(c[0]), "+f"(c[1]), "+f"(c[2]), "+f"(c[3])
        : "r"(a[0]), "r"(a[1]), "r"(a[2]), "r"(a[3]), "r"(b0), "r"(b1));
}
__device__ __forceinline__ uint32_t bf2bits(__nv_bfloat162 v) {
    return *reinterpret_cast<uint32_t*>(&v);
}
__device__ __forceinline__ void split8(float4 a, float4 b, uint4& H, uint4& L) {
    __nv_bfloat162 h0 = __floats2bfloat162_rn(a.x, a.y);
    __nv_bfloat162 h1 = __floats2bfloat162_rn(a.z, a.w);
    __nv_bfloat162 h2 = __floats2bfloat162_rn(b.x, b.y);
    __nv_bfloat162 h3 = __floats2bfloat162_rn(b.z, b.w);
    float2 f0 = __bfloat1622float2(h0), f1 = __bfloat1622float2(h1);
    float2 f2 = __bfloat1622float2(h2), f3 = __bfloat1622float2(h3);
    __nv_bfloat162 l0 = __floats2bfloat162_rn(a.x - f0.x, a.y - f0.y);
    __nv_bfloat162 l1 = __floats2bfloat162_rn(a.z - f1.x, a.w - f1.y);
    __nv_bfloat162 l2 = __floats2bfloat162_rn(b.x - f2.x, b.y - f2.y);
    __nv_bfloat162 l3 = __floats2bfloat162_rn(b.z - f3.x, b.w - f3.y);
    H.x = bf2bits(h0); H.y = bf2bits(h1); H.z = bf2bits(h2); H.w = bf2bits(h3);
    L.x = bf2bits(l0); L.y = bf2bits(l1); L.z = bf2bits(l2); L.w = bf2bits(l3);
}

// ---------------- split: fp32 -> bf16 [hi|hi|lo] (act) or [hi|lo|hi] (weight) ----------------
__global__ void split_kernel(const float* __restrict__ X, __nv_bfloat16* __restrict__ Y,
                             int K, int wmode) {
    size_t i = (size_t)blockIdx.x * blockDim.x + threadIdx.x;
    int K4 = K >> 2;
    size_t row = i / K4;
    int c4 = (int)(i - row * K4);
    float4 v = ((const float4*)X)[i];
    __nv_bfloat162 h0 = __floats2bfloat162_rn(v.x, v.y);
    __nv_bfloat162 h1 = __floats2bfloat162_rn(v.z, v.w);
    float2 hf0 = __bfloat1622float2(h0), hf1 = __bfloat1622float2(h1);
    __nv_bfloat162 l0 = __floats2bfloat162_rn(v.x - hf0.x, v.y - hf0.y);
    __nv_bfloat162 l1 = __floats2bfloat162_rn(v.z - hf1.x, v.w - hf1.y);
    uint2 Hh, Ll;
    Hh.x = bf2bits(h0); Hh.y = bf2bits(h1);
    Ll.x = bf2bits(l0); Ll.y = bf2bits(l1);
    __nv_bfloat16* yr = Y + row * (size_t)(3 * K) + c4 * 4;
    *(uint2*)yr = Hh;
    *(uint2*)(yr + K)     = wmode ? Ll : Hh;
    *(uint2*)(yr + 2 * K) = wmode ? Hh : Ll;
}

// ---------------- HMMA GEMM: 128x128x64 tile, 3-stage, 1 barrier/k-tile ----------------
constexpr int GSTAGES = 3;
constexpr int GAB_B = 128 * 144;      // A bytes per stage
constexpr int GSTG_B = 2 * GAB_B;     // 36864

__global__ void __launch_bounds__(256)
mma_gemm_kernel(const __nv_bfloat16* __restrict__ A, const __nv_bfloat16* __restrict__ W,
                int Kp, float* __restrict__ C, int ldc,
                const float* __restrict__ bias,
                const float* __restrict__ resid, int ldr, int act) {
    extern __shared__ __align__(16) char smem[];
    uint32_t sb = smem_u32(smem);
    int tid = threadIdx.x, lane = tid & 31, warp = tid >> 5;
    int wm = warp & 3, wn = warp >> 2;
    int brow = blockIdx.y * 128, bcol = blockIdx.x * 128;
    const char* gA = (const char*)(A + (size_t)brow * Kp);
    const char* gB = (const char*)(W + (size_t)bcol * Kp);
    int r0 = tid >> 1, cb = (tid & 1) * 4;

    auto load_stage = [&](int s, int kt) {
        uint32_t base = sb + s * GSTG_B;
        size_t gk = (size_t)kt * 128;
        const char* ga = gA + (size_t)r0 * Kp * 2 + gk;
        const char* gb = gB + (size_t)r0 * Kp * 2 + gk;
#pragma unroll
        for (int c = 0; c < 4; c++) {
            CP16(base + r0 * 144 + (cb + c) * 16,         ga + (cb + c) * 16);
            CP16(base + GAB_B + r0 * 144 + (cb + c) * 16, gb + (cb + c) * 16);
        }
        CP_COMMIT();
    };

    const int KT = Kp >> 6;
    load_stage(0, 0);
    load_stage(1, 1);

    float acc[2][8][4];
#pragma unroll
    for (int i = 0; i < 2; i++)
#pragma unroll
        for (int j = 0; j < 8; j++)
#pragma unroll
            for (int q = 0; q < 4; q++) acc[i][j][q] = 0.f;

    int a_r = lane & 15, a_c = (lane >> 4) * 8;
    int b_r = (lane & 7) + ((lane & 16) ? 8 : 0);
    int b_c = (lane & 8) ? 8 : 0;

    for (int kt = 0; kt < KT; kt++) {
        CP_WAIT1();
        __syncthreads();
        if (kt + 2 < KT) load_stage((kt + 2) % GSTAGES, kt + 2);
        else CP_COMMIT();
        uint32_t abase = sb + (kt % GSTAGES) * GSTG_B;
        uint32_t bbase = abase + GAB_B;
#pragma unroll
        for (int ks = 0; ks < 4; ks++) {
            uint32_t af[2][4], bf[4][4];
#pragma unroll
            for (int mi = 0; mi < 2; mi++)
                ldmx4(af[mi], abase + (wm * 32 + mi * 16 + a_r) * 144 + (ks * 16 + a_c) * 2);
#pragma unroll
            for (int nj = 0; nj < 4; nj++)
                ldmx4(bf[nj], bbase + (wn * 64 + nj * 16 + b_r) * 144 + (ks * 16 + b_c) * 2);
#pragma unroll
            for (int mi = 0; mi < 2; mi++)
#pragma unroll
                for (int nj = 0; nj < 4; nj++) {
                    mma16816(acc[mi][2 * nj],     af[mi], bf[nj][0], bf[nj][1]);
                    mma16816(acc[mi][2 * nj + 1], af[mi], bf[nj][2], bf[nj][3]);
                }
        }
    }

    int g = lane >> 2, qc = (lane & 3) * 2;
#pragma unroll
    for (int mi = 0; mi < 2; mi++)
#pragma unroll
        for (int half = 0; half < 2; half++) {
            size_t row = (size_t)brow + wm * 32 + mi * 16 + g + half * 8;
            float* crow = C + row * (size_t)ldc;
            const float* rrow = resid ? resid + row * (size_t)ldr : nullptr;
#pragma unroll
            for (int n8 = 0; n8 < 8; n8++) {
                int col = bcol + wn * 64 + n8 * 8 + qc;
                float v0 = acc[mi][n8][half * 2 + 0];
                float v1 = acc[mi][n8][half * 2 + 1];
                if (bias) {
                    float2 bb = *(const float2*)(bias + col);
                    v0 += bb.x; v1 += bb.y;
                }
                if (act == 1) {
                    v0 = fmaxf(v0, 0.f); v1 = fmaxf(v1, 0.f);
                } else if (act == 2) {
                    const float r2 = 0.70710678118654752f;
                    v0 = 0.5f * v0 * (1.f + erff(v0 * r2));
                    v1 = 0.5f * v1 * (1.f + erff(v1 * r2));
                }
                if (rrow) {
                    float2 rv = *(const float2*)(rrow + col);
                    v0 += rv.x; v1 += rv.y;
                }
                float2 o; o.x = v0; o.y = v1;
                *(float2*)(crow + col) = o;
            }
        }
}

// ---------------- tensor-core flash attention ----------------
// grid (S/128, NH, B), 256 thr (8 warps x 16 q-rows), 64-key tiles, double buffer.
constexpr int ATT_STG = 36864;   // Kh|Kl|Vh|Vl, each 64x144B
__global__ void __launch_bounds__(256, 1)
attn_mma_kernel(const float* __restrict__ Q, const float* __restrict__ K,
                const float* __restrict__ V, int ldi,
                float* __restrict__ O, int ldo) {
    extern __shared__ __align__(16) char smem[];
    uint32_t sb = smem_u32(smem);
    int tid = threadIdx.x, lane = tid & 31, warp = tid >> 5;
    int b = blockIdx.z, hh = blockIdx.y, q0 = blockIdx.x * 128;
    const float* Qg = Q + (size_t)(b * cS + q0) * ldi + hh * cHD;
    const float* Kg = K + (size_t)b * cS * ldi + hh * cHD;
    const float* Vg = V + (size_t)b * cS * ldi + hh * cHD;
    float* Og = O + (size_t)(b * cS + q0) * ldo + hh * cHD;

    int a_r = lane & 15, a_c = (lane >> 4) * 8;
    int kb_r = (lane & 7) + ((lane & 16) ? 8 : 0);
    int kb_c = (lane & 8) ? 8 : 0;

    // Phase 1: Q*0.125 -> smem hi/lo -> register fragments
    {
        const float* Qt = Qg + (size_t)(tid >> 1) * ldi + (tid & 1) * 32;
        uint32_t qoff = (uint32_t)(tid >> 1) * 144 + (tid & 1) * 64;
#pragma unroll
        for (int c = 0; c < 4; c++) {
            float4 a = *(const float4*)(Qt + c * 8);
            float4 bq = *(const float4*)(Qt + c * 8 + 4);
            a.x *= 0.125f; a.y *= 0.125f; a.z *= 0.125f; a.w *= 0.125f;
            bq.x *= 0.125f; bq.y *= 0.125f; bq.z *= 0.125f; bq.w *= 0.125f;
            uint4 H, L; split8(a, bq, H, L);
            *(uint4*)(smem + qoff + c * 16) = H;
            *(uint4*)(smem + 18432 + qoff + c * 16) = L;
        }
    }
    __syncthreads();
    uint32_t qh[4][4], ql[4][4];
#pragma unroll
    for (int t = 0; t < 4; t++) {
        uint32_t ad = sb + (warp * 16 + a_r) * 144 + (t * 16 + a_c) * 2;
        ldmx4(qh[t], ad);
        ldmx4(ql[t], ad + 18432);
    }
    __syncthreads();

    float of[8][4];
#pragma unroll
    for (int j = 0; j < 8; j++)
#pragma unroll
        for (int q = 0; q < 4; q++) of[j][q] = 0.f;
    float m0 = -1e30f, m1 = -1e30f, l0 = 0.f, l1 = 0.f;

    int key = tid >> 2, hb = (tid & 3) * 16;
    float4 kreg[4], vreg[4];
    auto load_tile = [&](int kt) {
        const float* Kt = Kg + (size_t)(kt * 64 + key) * ldi + hb;
        const float* Vt = Vg + (size_t)(kt * 64 + key) * ldi + hb;
#pragma unroll
        for (int i = 0; i < 4; i++) kreg[i] = *(const float4*)(Kt + i * 4);
#pragma unroll
        for (int i = 0; i < 4; i++) vreg[i] = *(const float4*)(Vt + i * 4);
    };
    auto store_tile = [&](int s) {
        uint32_t base = (uint32_t)s * ATT_STG + (uint32_t)key * 144 + hb * 2;
#pragma unroll
        for (int half = 0; half < 2; half++) {
            uint4 H, L;
            split8(kreg[2 * half], kreg[2 * half + 1], H, L);
            *(uint4*)(smem + base + half * 16) = H;
            *(uint4*)(smem + 9216 + base + half * 16) = L;
            split8(vreg[2 * half], vreg[2 * half + 1], H, L);
            *(uint4*)(smem + 18432 + base + half * 16) = H;
            *(uint4*)(smem + 27648 + base + half * 16) = L;
        }
    };

    load_tile(0);
    store_tile(0);
    __syncthreads();

    const int NT = cS / 64;
    for (int kt = 0; kt < NT; kt++) {
        if (kt + 1 < NT) load_tile(kt + 1);
        uint32_t stg = sb + (kt & 1) * ATT_STG;

        // S = Qs @ K^T (3-term)
        float sf[8][4];
#pragma unroll
        for (int j = 0; j < 8; j++)
#pragma unroll
            for (int q = 0; q < 4; q++) sf[j][q] = 0.f;
#pragma unroll
        for (int t = 0; t < 4; t++) {
            uint32_t bk[4][4];
#pragma unroll
            for (int j = 0; j < 4; j++)
                ldmx4(bk[j], stg + (j * 16 + kb_r) * 144 + (t * 16 + kb_c) * 2);
#pragma unroll
            for (int j = 0; j < 4; j++) {
                mma16816(sf[2 * j],     qh[t], bk[j][0], bk[j][1]);
                mma16816(sf[2 * j + 1], qh[t], bk[j][2], bk[j][3]);
                mma16816(sf[2 * j],     ql[t], bk[j][0], bk[j][1]);
                mma16816(sf[2 * j + 1], ql[t], bk[j][2], bk[j][3]);
            }
#pragma unroll
            for (int j = 0; j < 4; j++)
                ldmx4(bk[j], stg + 9216 + (j * 16 + kb_r) * 144 + (t * 16 + kb_c) * 2);
#pragma unroll
            for (int j = 0; j < 4; j++) {
                mma16816(sf[2 * j],     qh[t], bk[j][0], bk[j][1]);
                mma16816(sf[2 * j + 1], qh[t], bk[j][2], bk[j][3]);
            }
        }

        // online softmax: rows r (regs 0,1) and r+8 (regs 2,3); quad-reduce over lane&3
        float mx0 = -1e30f, mx1 = -1e30f;
#pragma unroll
        for (int j = 0; j < 8; j++) {
            mx0 = fmaxf(mx0, fmaxf(sf[j][0], sf[j][1]));
            mx1 = fmaxf(mx1, fmaxf(sf[j][2], sf[j][3]));
        }
        mx0 = fmaxf(mx0, __shfl_xor_sync(0xffffffffu, mx0, 1));
        mx0 = fmaxf(mx0, __shfl_xor_sync(0xffffffffu, mx0, 2));
        mx1 = fmaxf(mx1, __shfl_xor_sync(0xffffffffu, mx1, 1));
        mx1 = fmaxf(mx1, __shfl_xor_sync(0xffffffffu, mx1, 2));
        float mn0 = fmaxf(m0, mx0), mn1 = fmaxf(m1, mx1);
        float c0 = __expf(m0 - mn0), c1 = __expf(m1 - mn1);
        float rs0 = 0.f, rs1 = 0.f;
        uint32_t pk[4][4];
#pragma unroll
        for (int j = 0; j < 8; j++) {
            float p00 = __expf(sf[j][0] - mn0), p01 = __expf(sf[j][1] - mn0);
            float p10 = __expf(sf[j][2] - mn1), p11 = __expf(sf[j][3] - mn1);
            __nv_bfloat162 pb0 = __floats2bfloat162_rn(p00, p01);
            __nv_bfloat162 pb1 = __floats2bfloat162_rn(p10, p11);
            float2 r0 = __bfloat1622float2(pb0), r1 = __bfloat1622float2(pb1);
            rs0 += r0.x + r0.y; rs1 += r1.x + r1.y;
            pk[j >> 1][(j & 1) * 2 + 0] = bf2bits(pb0);
            pk[j >> 1][(j & 1) * 2 + 1] = bf2bits(pb1);
        }
        rs0 += __shfl_xor_sync(0xffffffffu, rs0, 1);
        rs0 += __shfl_xor_sync(0xffffffffu, rs0, 2);
        rs1 += __shfl_xor_sync(0xffffffffu, rs1, 1);
        rs1 += __shfl_xor_sync(0xffffffffu, rs1, 2);
        l0 = l0 * c0 + rs0; l1 = l1 * c1 + rs1;
#pragma unroll
        for (int j = 0; j < 8; j++) {
            of[j][0] *= c0; of[j][1] *= c0; of[j][2] *= c1; of[j][3] *= c1;
        }
        m0 = mn0; m1 = mn1;

        // O += P @ V (2-term, trans ldmatrix for V)
#pragma unroll
        for (int t = 0; t < 4; t++) {
            uint32_t bv[4][4];
#pragma unroll
            for (int g = 0; g < 4; g++)
                ldmx4t(bv[g], stg + 18432 + (t * 16 + a_r) * 144 + (g * 16 + a_c) * 2);
#pragma unroll
            for (int g = 0; g < 4; g++) {
                mma16816(of[2 * g],     pk[t], bv[g][0], bv[g][1]);
                mma16816(of[2 * g + 1], pk[t], bv[g][2], bv[g][3]);
            }
#pragma unroll
            for (int g = 0; g < 4; g++)
                ldmx4t(bv[g], stg + 27648 + (t * 16 + a_r) * 144 + (g * 16 + a_c) * 2);
#pragma unroll
            for (int g = 0; g < 4; g++) {
                mma16816(of[2 * g],     pk[t], bv[g][0], bv[g][1]);
                mma16816(of[2 * g + 1], pk[t], bv[g][2], bv[g][3]);
            }
        }

        if (kt + 1 < NT) store_tile((kt + 1) & 1);
        __syncthreads();
    }

    float i0 = 1.f / l0, i1 = 1.f / l1;
    int rr = lane >> 2, cc = (lane & 3) * 2;
#pragma unroll
    for (int j = 0; j < 8; j++) {
        int col = j * 8 + cc;
        float2 o0; o0.x = of[j][0] * i0; o0.y = of[j][1] * i0;
        float2 o1; o1.x = of[j][2] * i1; o1.y = of[j][3] * i1;
        *(float2*)(Og + (size_t)(warp * 16 + rr) * ldo + col) = o0;
        *(float2*)(Og + (size_t)(warp * 16 + rr + 8) * ldo + col) = o1;
    }
}

// ---------------- LayerNorm ----------------
__global__ void ln_kernel(const float* __restrict__ x, const float* __restrict__ w,
                          const float* __restrict__ b, float* __restrict__ y) {
    int row = blockIdx.x, t = threadIdx.x;
    float4 v = ((const float4*)(x + (size_t)row * cH))[t];
    float s1 = v.x + v.y + v.z + v.w;
    float s2 = v.x * v.x + v.y * v.y + v.z * v.z + v.w * v.w;
#pragma unroll
    for (int o = 16; o > 0; o >>= 1) {
        s1 += __shfl_xor_sync(0xffffffffu, s1, o);
        s2 += __shfl_xor_sync(0xffffffffu, s2, o);
    }
    __shared__ float sm1[8], sm2[8];
    __shared__ float s_mean, s_rstd;
    if ((t & 31) == 0) { sm1[t >> 5] = s1; sm2[t >> 5] = s2; }
    __syncthreads();
    if (t == 0) {
        float a = 0.f, c = 0.f;
#pragma unroll
        for (int i = 0; i < 8; i++) { a += sm1[i]; c += sm2[i]; }
        float mean = a * (1.0f / cH);
        float var  = c * (1.0f / cH) - mean * mean;
        s_mean = mean; s_rstd = rsqrtf(var + 1e-5f);
    }
    __syncthreads();
    float mean = s_mean, rstd = s_rstd;
    float4 wv = ((const float4*)w)[t];
    float4 bv = ((const float4*)b)[t];
    float4 o;
    o.x = (v.x - mean) * rstd * wv.x + bv.x;
    o.y = (v.y - mean) * rstd * wv.y + bv.y;
    o.z = (v.z - mean) * rstd * wv.z + bv.z;
    o.w = (v.w - mean) * rstd * wv.w + bv.w;
    ((float4*)(y + (size_t)row * cH))[t] = o;
}

// ---------------- small kernels ----------------
__global__ void select_kernel(const float* __restrict__ h1, float* __restrict__ h,
                              const int* __restrict__ li) {
    int L = *li;
    if ((L % 4 == 0) && L > 0) return;
    size_t i = (size_t)blockIdx.x * blockDim.x + threadIdx.x;
    ((float4*)h)[i] = ((const float4*)h1)[i];
}

__global__ void pool_kernel(const float* __restrict__ hbuf, float* __restrict__ pooled) {
    int b = blockIdx.y;
    int col = blockIdx.x * blockDim.x + threadIdx.x;
    const float* p = hbuf + (size_t)b * cS * cH + col;
    float a0 = 0, a1 = 0, a2 = 0, a3 = 0;
    for (int s = 0; s < cS; s += 4) {
        a0 += p[(size_t)s * cH];
        a1 += p[(size_t)(s + 1) * cH];
        a2 += p[(size_t)(s + 2) * cH];
        a3 += p[(size_t)(s + 3) * cH];
    }
    pooled[b * cH + col] = (a0 + a1 + a2 + a3) * (1.0f / cS);
}

__global__ void allocretr_kernel(const float* __restrict__ pooled,
                                 const float* __restrict__ aw, const float* __restrict__ ab,
                                 const float* __restrict__ rw, const float* __restrict__ rb,
                                 float* __restrict__ alloc_o, float* __restrict__ retr_o) {
    int b = blockIdx.y, which = blockIdx.x;
    const float* w  = which ? rw : aw;
    const float* bi = which ? rb : ab;
    float* out = which ? retr_o : alloc_o;
    int n = threadIdx.x;
    const float* p  = pooled + b * cH;
    const float* wr = w + (size_t)n * cH;
    float acc = bi[n];
    for (int k = 0; k < cH; k += 4)
        acc += p[k] * wr[k] + p[k + 1] * wr[k + 1] + p[k + 2] * wr[k + 2] + p[k + 3] * wr[k + 3];
    __shared__ float red[cMB];
    red[n] = acc; __syncthreads();
    for (int o = 64; o > 0; o >>= 1) { if (n < o) red[n] = fmaxf(red[n], red[n + o]); __syncthreads(); }
    float mx = red[0]; __syncthreads();
    float e = __expf(acc - mx);
    red[n] = e; __syncthreads();
    for (int o = 64; o > 0; o >>= 1) { if (n < o) red[n] += red[n + o]; __syncthreads(); }
    out[b * cMB + n] = e / red[0];
}

__global__ void retrieve_kernel(const float* __restrict__ retr_o,
                                const float* __restrict__ memb, float* __restrict__ retrv) {
    int b = blockIdx.y;
    int col = blockIdx.x * blockDim.x + threadIdx.x;
    float acc = 0.f;
#pragma unroll 4
    for (int r = 0; r < cMB; r++) acc += retr_o[b * cMB + r] * memb[(size_t)r * cH + col];
    retrv[b * cH + col] = acc;
}

__global__ void addmem_kernel(float* __restrict__ h, const float* __restrict__ retrv,
                              const float* __restrict__ msc, const int* __restrict__ li) {
    float sc = msc[*li];
    size_t idx = ((size_t)blockIdx.x * blockDim.x + threadIdx.x) * 4;
    int b = (int)(idx / ((size_t)cS * cH));
    int c = (int)(idx % cH);
    float4 r = *(const float4*)(retrv + b * cH + c);
    float4 v = *(float4*)(h + idx);
    v.x += r.x * sc; v.y += r.y * sc; v.z += r.z * sc; v.w += r.w * sc;
    *(float4*)(h + idx) = v;
}

__global__ void pooled2_kernel(const float* __restrict__ pooled, const float* __restrict__ retrv,
                               const float* __restrict__ msc, const int* __restrict__ li,
                               float* __restrict__ pooled2) {
    float sc = msc[*li];
    int i = blockIdx.x * blockDim.x + threadIdx.x;
    pooled2[i] = pooled[i] + retrv[i] * sc;
}

__global__ void upd_kernel(const float* __restrict__ pooled2, const float* __restrict__ uw,
                           const float* __restrict__ ub, float* __restrict__ sig) {
    int b = blockIdx.y;
    int n = blockIdx.x * blockDim.x + threadIdx.x;
    const float* p = pooled2 + b * cH;
    const float* w = uw + (size_t)n * cH;
    float acc = ub[n];
    for (int k = 0; k < cH; k += 4)
        acc += p[k] * w[k] + p[k + 1] * w[k + 1] + p[k + 2] * w[k + 2] + p[k + 3] * w[k + 3];
    sig[b * cH + n] = 1.f / (1.f + __expf(-acc));
}

__global__ void topk_kernel(const float* __restrict__ alloc_o, int* __restrict__ top) {
    int b = blockIdx.x;
    if (threadIdx.x != 0) return;
    float v[cMB];
    for (int i = 0; i < cMB; i++) v[i] = alloc_o[b * cMB + i];
    for (int k = 0; k < cTOPK; k++) {
        int arg = 0; float best = v[0];
        for (int i = 1; i < cMB; i++) if (v[i] > best) { best = v[i]; arg = i; }
        top[b * cTOPK + k] = arg;
        v[arg] = -1e30f;
    }
}

__global__ void scatter_kernel(const int* __restrict__ top, const float* __restrict__ sig,
                               const float* __restrict__ memb, float* __restrict__ outm) {
    int r = blockIdx.x;
    __shared__ int sel;
    if (threadIdx.x == 0) {
        int s = -1;
        for (int bb = 0; bb < cB; bb++)
            for (int k = 0; k < cTOPK; k++)
                if (top[bb * cTOPK + k] == r) s = bb;
        sel = s;
    }
    __syncthreads();
    const float* src = (sel >= 0) ? (sig + (size_t)sel * cH) : (memb + (size_t)r * cH);
    for (int c = threadIdx.x; c < cH; c += blockDim.x)
        outm[(size_t)r * cH + c] = src[c];
}

// ---------------- launch ----------------
extern "C" void kernel_launch(void* const* d_in, const int* in_sizes, int n_in,
                              void* d_out, int out_size) {
    (void)in_sizes; (void)n_in; (void)out_size;
    const float* x    = (const float*)d_in[0];
    const float* ln1w = (const float*)d_in[1];
    const float* ln1b = (const float*)d_in[2];
    const float* ln2w = (const float*)d_in[3];
    const float* ln2b = (const float*)d_in[4];
    const float* wq   = (const float*)d_in[5];
    const float* wk   = (const float*)d_in[6];
    const float* wv   = (const float*)d_in[7];
    const float* wo   = (const float*)d_in[8];
    const float* ad1  = (const float*)d_in[9];
    const float* ad2  = (const float*)d_in[10];
    const float* memb = (const float*)d_in[11];
    const float* aw   = (const float*)d_in[12];
    const float* ab   = (const float*)d_in[13];
    const float* rw   = (const float*)d_in[14];
    const float* rb   = (const float*)d_in[15];
    const float* uw   = (const float*)d_in[16];
    const float* ub   = (const float*)d_in[17];
    const float* msc  = (const float*)d_in[18];
    const float* aiw  = (const float*)d_in[19];
    const float* aib  = (const float*)d_in[20];
    const float* aow  = (const float*)d_in[21];
    const float* aob  = (const float*)d_in[22];
    const float* m1w  = (const float*)d_in[23];
    const float* m1b  = (const float*)d_in[24];
    const float* m2w  = (const float*)d_in[25];
    const float* m2b  = (const float*)d_in[26];
    const int*   li   = (const int*)d_in[27];
    float* out  = (float*)d_out;
    float* outm = out + (size_t)cM * cH;

    float *p_h1, *p_ao, *p_t1, *p_t2, *p_h, *p_h4, *p_qkv, *p_ff;
    float *p_pooled, *p_pooled2, *p_alloc, *p_retr, *p_retrv, *p_sig;
    int* p_top;
    __nv_bfloat16 *p_sA, *p_sF, *p_sW;
    cudaGetSymbolAddress((void**)&p_h1, g_h1);
    cudaGetSymbolAddress((void**)&p_ao, g_ao);
    cudaGetSymbolAddress((void**)&p_t1, g_t1);
    cudaGetSymbolAddress((void**)&p_t2, g_t2);
    cudaGetSymbolAddress((void**)&p_h, g_h);
    cudaGetSymbolAddress((void**)&p_h4, g_h4);
    cudaGetSymbolAddress((void**)&p_qkv, g_qkv);
    cudaGetSymbolAddress((void**)&p_ff, g_ff);
    cudaGetSymbolAddress((void**)&p_pooled, g_pooled);
    cudaGetSymbolAddress((void**)&p_pooled2, g_pooled2);
    cudaGetSymbolAddress((void**)&p_alloc, g_allocp);
    cudaGetSymbolAddress((void**)&p_retr, g_retrp);
    cudaGetSymbolAddress((void**)&p_retrv, g_retrv);
    cudaGetSymbolAddress((void**)&p_sig, g_sig);
    cudaGetSymbolAddress((void**)&p_top, g_top);
    cudaGetSymbolAddress((void**)&p_sA, g_sA);
    cudaGetSymbolAddress((void**)&p_sF, g_sF);
    cudaGetSymbolAddress((void**)&p_sW, g_sW);

    const int GSM = GSTAGES * GSTG_B;   // 110592
    cudaFuncSetAttribute(mma_gemm_kernel, cudaFuncAttributeMaxDynamicSharedMemorySize, GSM);
    const int ASM = 2 * ATT_STG;        // 73728
    cudaFuncSetAttribute(attn_mma_kernel, cudaFuncAttributeMaxDynamicSharedMemorySize, ASM);

    dim3 gattn(cS / 128, cNH, cB);
    auto splitA = [&](const float* src, __nv_bfloat16* dst, int K) {
        split_kernel<<<(int)(((size_t)cM * K / 4) / 256), 256>>>(src, dst, K, 0);
    };
    auto splitW = [&](const float* src, __nv_bfloat16* dst, int N, int K) {
        split_kernel<<<(int)(((size_t)N * K / 4) / 256), 256>>>(src, dst, K, 1);
    };

    ln_kernel<<<cM, 256>>>(x, ln1w, ln1b, p_h1);
    // --- recycle branch (layer_idx=4 active; select_kernel handles the other case) ---
    splitA(p_h1, p_sA, cH);
    splitW(wq, p_sW,                          cH, cH);
    splitW(wk, p_sW + (size_t)1024 * 3072,    cH, cH);
    splitW(wv, p_sW + (size_t)2048 * 3072,    cH, cH);
    mma_gemm_kernel<<<dim3(24, 64), 256, GSM>>>(p_sA, p_sW, 3072, p_qkv, 3 * cH, nullptr, nullptr, 0, 0);
    attn_mma_kernel<<<gattn, 256, ASM>>>(p_qkv, p_qkv + cH, p_qkv + 2 * cH, 3 * cH, p_ao, cH);
    splitA(p_ao, p_sA, cH);
    splitW(wo, p_sW, cH, cH);
    mma_gemm_kernel<<<dim3(8, 64), 256, GSM>>>(p_sA, p_sW, 3072, p_t1, cH, nullptr, nullptr, 0, 0);
    splitA(p_t1, p_sA, cH);
    splitW(ad1, p_sW, cH / 4, cH);
    mma_gemm_kernel<<<dim3(2, 64), 256, GSM>>>(p_sA, p_sW, 3072, p_t2, cH / 4, nullptr, nullptr, 0, 1);
    splitA(p_t2, p_sA, cH / 4);
    splitW(ad2, p_sW, cH, cH / 4);
    mma_gemm_kernel<<<dim3(8, 64), 256, GSM>>>(p_sA, p_sW, 768, p_h, cH, nullptr, nullptr, 0, 0);
    select_kernel<<<cM * cH / 4 / 256, 256>>>(p_h1, p_h, li);
    // --- memory manager ---
    pool_kernel<<<dim3(cH / 256, cB), 256>>>(p_h, p_pooled);
    allocretr_kernel<<<dim3(2, cB), cMB>>>(p_pooled, aw, ab, rw, rb, p_alloc, p_retr);
    retrieve_kernel<<<dim3(cH / 256, cB), 256>>>(p_retr, memb, p_retrv);
    addmem_kernel<<<cM * cH / 4 / 256, 256>>>(p_h, p_retrv, msc, li);
    pooled2_kernel<<<cB * cH / 256, 256>>>(p_pooled, p_retrv, msc, li, p_pooled2);
    upd_kernel<<<dim3(cH / 128, cB), 128>>>(p_pooled2, uw, ub, p_sig);
    topk_kernel<<<cB, 32>>>(p_alloc, p_top);
    scatter_kernel<<<cMB, 256>>>(p_top, p_sig, memb, outm);
    // --- self attention ---
    splitA(p_h, p_sA, cH);
    splitW(aiw, p_sW, 3 * cH, cH);
    mma_gemm_kernel<<<dim3(24, 64), 256, GSM>>>(p_sA, p_sW, 3072, p_qkv, 3 * cH, aib, nullptr, 0, 0);
    attn_mma_kernel<<<gattn, 256, ASM>>>(p_qkv, p_qkv + cH, p_qkv + 2 * cH, 3 * cH, p_ao, cH);
    splitA(p_ao, p_sA, cH);
    splitW(aow, p_sW, cH, cH);
    mma_gemm_kernel<<<dim3(8, 64), 256, GSM>>>(p_sA, p_sW, 3072, p_h4, cH, aob, x, cH, 0);
    // --- MLP ---
    ln_kernel<<<cM, 256>>>(p_h4, ln2w, ln2b, p_h1);
    splitA(p_h1, p_sA, cH);
    splitW(m1w, p_sW, cFF, cH);
    mma_gemm_kernel<<<dim3(32, 64), 256, GSM>>>(p_sA, p_sW, 3072, p_ff, cFF, m1b, nullptr, 0, 2);
    splitA(p_ff, p_sF, cFF);
    splitW(m2w, p_sW, cH, cFF);
    mma_gemm_kernel<<<dim3(8, 64), 256, GSM>>>(p_sF, p_sW, 12288, out, cH, m2b, p_h4, cH, 0);
}

// round 11
// speedup vs baseline: 2.0853x; 1.0038x over previous
#include <cuda_runtime.h>
#include <cuda_bf16.h>
#include <cstddef>
#include <cstdint>

constexpr int cB = 8, cS = 1024, cH = 1024, cNH = 16, cHD = 64;
constexpr int cMB = 128, cTOPK = 16, cFF = 4096;
constexpr int cM = cB * cS;

// ---------------- scratch ----------------
__device__ float g_h1 [(size_t)cM * cH];
__device__ float g_h  [(size_t)cM * cH];
__device__ float g_h4 [(size_t)cM * cH];
__device__ float g_qkv[(size_t)cM * 3 * cH];
__device__ float g_pooled [cB * cH];
__device__ float g_pooled2[cB * cH];
__device__ float g_allocp [cB * cMB];
__device__ float g_retrp  [cB * cMB];
__device__ float g_retrv  [cB * cH];
__device__ float g_sig    [cB * cH];
__device__ int   g_top    [cB * cTOPK];
__device__ __nv_bfloat16 g_sA[(size_t)cM * 3 * cH];
__device__ __nv_bfloat16 g_sF[(size_t)cM * 3 * cFF];   // also reused as sB (t1 split)
__device__ __nv_bfloat16 g_sW[(size_t)cFF * 3 * cH];

// ---------------- helpers ----------------
__device__ __forceinline__ uint32_t smem_u32(const void* p) {
    uint32_t a;
    asm("{ .reg .u64 t; cvta.to.shared.u64 t, %1; cvt.u32.u64 %0, t; }" : "=r"(a) : "l"(p));
    return a;
}
#define CP16(dst, src) \
    asm volatile("cp.async.cg.shared.global [%0], [%1], 16;" :: "r"(dst), "l"(src))
#define CP_COMMIT() asm volatile("cp.async.commit_group;" ::: "memory")
#define CP_WAIT1() asm volatile("cp.async.wait_group 1;" ::: "memory")

__device__ __forceinline__ void ldmx4(uint32_t* r, uint32_t addr) {
    asm volatile("ldmatrix.sync.aligned.m8n8.x4.shared.b16 {%0,%1,%2,%3}, [%4];"
                 : "=r"(r[0]), "=r"(r[1]), "=r"(r[2]), "=r"(r[3]) : "r"(addr));
}
__device__ __forceinline__ void ldmx4t(uint32_t* r, uint32_t addr) {
    asm volatile("ldmatrix.sync.aligned.m8n8.x4.trans.shared.b16 {%0,%1,%2,%3}, [%4];"
                 : "=r"(r[0]), "=r"(r[1]), "=r"(r[2]), "=r"(r[3]) : "r"(addr));
}
__device__ __forceinline__ void mma16816(float* c, const uint32_t* a, uint32_t b0, uint32_t b1) {
    asm volatile(
        "mma.sync.aligned.m16n8k16.row.col.f32.bf16.bf16.f32 "
        "{%0,%1,%2,%3}, {%4,%5,%6,%7}, {%8,%9}, {%0,%1,%2,%3};"
        : "+f"(c[0]), "+f"(c[1]), "+f"(c[2]), "+f"(c[3])
        : "r"(a[0]), "r"(a[1]), "r"(a[2]), "r"(a[3]), "r"(b0), "r"(b1));
}
__device__ __forceinline__ uint32_t bf2bits(__nv_bfloat162 v) {
    return *reinterpret_cast<uint32_t*>(&v);
}
__device__ __forceinline__ void split8(float4 a, float4 b, uint4& H, uint4& L) {
    __nv_bfloat162 h0 = __floats2bfloat162_rn(a.x, a.y);
    __nv_bfloat162 h1 = __floats2bfloat162_rn(a.z, a.w);
    __nv_bfloat162 h2 = __floats2bfloat162_rn(b.x, b.y);
    __nv_bfloat162 h3 = __floats2bfloat162_rn(b.z, b.w);
    float2 f0 = __bfloat1622float2(h0), f1 = __bfloat1622float2(h1);
    float2 f2 = __bfloat1622float2(h2), f3 = __bfloat1622float2(h3);
    __nv_bfloat162 l0 = __floats2bfloat162_rn(a.x - f0.x, a.y - f0.y);
    __nv_bfloat162 l1 = __floats2bfloat162_rn(a.z - f1.x, a.w - f1.y);
    __nv_bfloat162 l2 = __floats2bfloat162_rn(b.x - f2.x, b.y - f2.y);
    __nv_bfloat162 l3 = __floats2bfloat162_rn(b.z - f3.x, b.w - f3.y);
    H.x = bf2bits(h0); H.y = bf2bits(h1); H.z = bf2bits(h2); H.w = bf2bits(h3);
    L.x = bf2bits(l0); L.y = bf2bits(l1); L.z = bf2bits(l2); L.w = bf2bits(l3);
}
// split a float2 -> hi bf162 + lo bf162
__device__ __forceinline__ void split2(float v0, float v1, uint32_t& H, uint32_t& L) {
    __nv_bfloat162 h = __floats2bfloat162_rn(v0, v1);
    float2 hf = __bfloat1622float2(h);
    __nv_bfloat162 l = __floats2bfloat162_rn(v0 - hf.x, v1 - hf.y);
    H = bf2bits(h); L = bf2bits(l);
}

// ---------------- split: fp32 -> bf16 [hi|hi|lo] (act) or [hi|lo|hi] (weight) ----------------
__global__ void split_kernel(const float* __restrict__ X, __nv_bfloat16* __restrict__ Y,
                             int K, int wmode) {
    size_t i = (size_t)blockIdx.x * blockDim.x + threadIdx.x;
    int K4 = K >> 2;
    size_t row = i / K4;
    int c4 = (int)(i - row * K4);
    float4 v = ((const float4*)X)[i];
    __nv_bfloat162 h0 = __floats2bfloat162_rn(v.x, v.y);
    __nv_bfloat162 h1 = __floats2bfloat162_rn(v.z, v.w);
    float2 hf0 = __bfloat1622float2(h0), hf1 = __bfloat1622float2(h1);
    __nv_bfloat162 l0 = __floats2bfloat162_rn(v.x - hf0.x, v.y - hf0.y);
    __nv_bfloat162 l1 = __floats2bfloat162_rn(v.z - hf1.x, v.w - hf1.y);
    uint2 Hh, Ll;
    Hh.x = bf2bits(h0); Hh.y = bf2bits(h1);
    Ll.x = bf2bits(l0); Ll.y = bf2bits(l1);
    __nv_bfloat16* yr = Y + row * (size_t)(3 * K) + c4 * 4;
    *(uint2*)yr = Hh;
    *(uint2*)(yr + K)     = wmode ? Ll : Hh;
    *(uint2*)(yr + 2 * K) = wmode ? Hh : Ll;
}

// ---------------- HMMA GEMM: 128x128x64 tile, 3-stage, 1 barrier/k-tile ----------------
// Output: either fp32 C (ldc) or bf16 split Cs ([M, 3*Kn] hi|hi|lo), after bias/act/resid.
constexpr int GSTAGES = 3;
constexpr int GAB_B = 128 * 144;
constexpr int GSTG_B = 2 * GAB_B;

__global__ void __launch_bounds__(256)
mma_gemm_kernel(const __nv_bfloat16* __restrict__ A, const __nv_bfloat16* __restrict__ W,
                int Kp, float* __restrict__ C, int ldc,
                __nv_bfloat16* __restrict__ Cs, int Kn,
                const float* __restrict__ bias,
                const float* __restrict__ resid, int ldr, int act) {
    extern __shared__ __align__(16) char smem[];
    uint32_t sb = smem_u32(smem);
    int tid = threadIdx.x, lane = tid & 31, warp = tid >> 5;
    int wm = warp & 3, wn = warp >> 2;
    int brow = blockIdx.y * 128, bcol = blockIdx.x * 128;
    const char* gA = (const char*)(A + (size_t)brow * Kp);
    const char* gB = (const char*)(W + (size_t)bcol * Kp);
    int r0 = tid >> 1, cb = (tid & 1) * 4;

    auto load_stage = [&](int s, int kt) {
        uint32_t base = sb + s * GSTG_B;
        size_t gk = (size_t)kt * 128;
        const char* ga = gA + (size_t)r0 * Kp * 2 + gk;
        const char* gb = gB + (size_t)r0 * Kp * 2 + gk;
#pragma unroll
        for (int c = 0; c < 4; c++) {
            CP16(base + r0 * 144 + (cb + c) * 16,         ga + (cb + c) * 16);
            CP16(base + GAB_B + r0 * 144 + (cb + c) * 16, gb + (cb + c) * 16);
        }
        CP_COMMIT();
    };

    const int KT = Kp >> 6;
    load_stage(0, 0);
    load_stage(1, 1);

    float acc[2][8][4];
#pragma unroll
    for (int i = 0; i < 2; i++)
#pragma unroll
        for (int j = 0; j < 8; j++)
#pragma unroll
            for (int q = 0; q < 4; q++) acc[i][j][q] = 0.f;

    int a_r = lane & 15, a_c = (lane >> 4) * 8;
    int b_r = (lane & 7) + ((lane & 16) ? 8 : 0);
    int b_c = (lane & 8) ? 8 : 0;

    for (int kt = 0; kt < KT; kt++) {
        CP_WAIT1();
        __syncthreads();
        if (kt + 2 < KT) load_stage((kt + 2) % GSTAGES, kt + 2);
        else CP_COMMIT();
        uint32_t abase = sb + (kt % GSTAGES) * GSTG_B;
        uint32_t bbase = abase + GAB_B;
#pragma unroll
        for (int ks = 0; ks < 4; ks++) {
            uint32_t af[2][4], bf[4][4];
#pragma unroll
            for (int mi = 0; mi < 2; mi++)
                ldmx4(af[mi], abase + (wm * 32 + mi * 16 + a_r) * 144 + (ks * 16 + a_c) * 2);
#pragma unroll
            for (int nj = 0; nj < 4; nj++)
                ldmx4(bf[nj], bbase + (wn * 64 + nj * 16 + b_r) * 144 + (ks * 16 + b_c) * 2);
#pragma unroll
            for (int mi = 0; mi < 2; mi++)
#pragma unroll
                for (int nj = 0; nj < 4; nj++) {
                    mma16816(acc[mi][2 * nj],     af[mi], bf[nj][0], bf[nj][1]);
                    mma16816(acc[mi][2 * nj + 1], af[mi], bf[nj][2], bf[nj][3]);
                }
        }
    }

    int g = lane >> 2, qc = (lane & 3) * 2;
#pragma unroll
    for (int mi = 0; mi < 2; mi++)
#pragma unroll
        for (int half = 0; half < 2; half++) {
            size_t row = (size_t)brow + wm * 32 + mi * 16 + g + half * 8;
            const float* rrow = resid ? resid + row * (size_t)ldr : nullptr;
#pragma unroll
            for (int n8 = 0; n8 < 8; n8++) {
                int col = bcol + wn * 64 + n8 * 8 + qc;
                float v0 = acc[mi][n8][half * 2 + 0];
                float v1 = acc[mi][n8][half * 2 + 1];
                if (bias) {
                    float2 bb = *(const float2*)(bias + col);
                    v0 += bb.x; v1 += bb.y;
                }
                if (act == 1) {
                    v0 = fmaxf(v0, 0.f); v1 = fmaxf(v1, 0.f);
                } else if (act == 2) {
                    const float r2 = 0.70710678118654752f;
                    v0 = 0.5f * v0 * (1.f + erff(v0 * r2));
                    v1 = 0.5f * v1 * (1.f + erff(v1 * r2));
                }
                if (rrow) {
                    float2 rv = *(const float2*)(rrow + col);
                    v0 += rv.x; v1 += rv.y;
                }
                if (Cs) {
                    uint32_t H, L; split2(v0, v1, H, L);
                    __nv_bfloat16* cr = Cs + row * (size_t)(3 * Kn) + col;
                    *(uint32_t*)cr = H;
                    *(uint32_t*)(cr + Kn) = H;
                    *(uint32_t*)(cr + 2 * Kn) = L;
                } else {
                    float2 o; o.x = v0; o.y = v1;
                    *(float2*)(C + row * (size_t)ldc + col) = o;
                }
            }
        }
}

// ---------------- tensor-core flash attention (bf16 split output) ----------------
constexpr int ATT_STG = 36864;
__global__ void __launch_bounds__(256, 1)
attn_mma_kernel(const float* __restrict__ Q, const float* __restrict__ K,
                const float* __restrict__ V, int ldi,
                __nv_bfloat16* __restrict__ Os) {   // [M, 3072] hi|hi|lo
    extern __shared__ __align__(16) char smem[];
    uint32_t sb = smem_u32(smem);
    int tid = threadIdx.x, lane = tid & 31, warp = tid >> 5;
    int b = blockIdx.z, hh = blockIdx.y, q0 = blockIdx.x * 128;
    const float* Qg = Q + (size_t)(b * cS + q0) * ldi + hh * cHD;
    const float* Kg = K + (size_t)b * cS * ldi + hh * cHD;
    const float* Vg = V + (size_t)b * cS * ldi + hh * cHD;
    __nv_bfloat16* Og = Os + (size_t)(b * cS + q0) * 3072 + hh * cHD;

    int a_r = lane & 15, a_c = (lane >> 4) * 8;
    int kb_r = (lane & 7) + ((lane & 16) ? 8 : 0);
    int kb_c = (lane & 8) ? 8 : 0;

    // Phase 1: Q*0.125 -> smem hi/lo -> register fragments
    {
        const float* Qt = Qg + (size_t)(tid >> 1) * ldi + (tid & 1) * 32;
        uint32_t qoff = (uint32_t)(tid >> 1) * 144 + (tid & 1) * 64;
#pragma unroll
        for (int c = 0; c < 4; c++) {
            float4 a = *(const float4*)(Qt + c * 8);
            float4 bq = *(const float4*)(Qt + c * 8 + 4);
            a.x *= 0.125f; a.y *= 0.125f; a.z *= 0.125f; a.w *= 0.125f;
            bq.x *= 0.125f; bq.y *= 0.125f; bq.z *= 0.125f; bq.w *= 0.125f;
            uint4 H, L; split8(a, bq, H, L);
            *(uint4*)(smem + qoff + c * 16) = H;
            *(uint4*)(smem + 18432 + qoff + c * 16) = L;
        }
    }
    __syncthreads();
    uint32_t qh[4][4], ql[4][4];
#pragma unroll
    for (int t = 0; t < 4; t++) {
        uint32_t ad = sb + (warp * 16 + a_r) * 144 + (t * 16 + a_c) * 2;
        ldmx4(qh[t], ad);
        ldmx4(ql[t], ad + 18432);
    }
    __syncthreads();

    float of[8][4];
#pragma unroll
    for (int j = 0; j < 8; j++)
#pragma unroll
        for (int q = 0; q < 4; q++) of[j][q] = 0.f;
    float m0 = -1e30f, m1 = -1e30f, l0 = 0.f, l1 = 0.f;

    int key = tid >> 2, hb = (tid & 3) * 16;
    float4 kreg[4], vreg[4];
    auto load_tile = [&](int kt) {
        const float* Kt = Kg + (size_t)(kt * 64 + key) * ldi + hb;
        const float* Vt = Vg + (size_t)(kt * 64 + key) * ldi + hb;
#pragma unroll
        for (int i = 0; i < 4; i++) kreg[i] = *(const float4*)(Kt + i * 4);
#pragma unroll
        for (int i = 0; i < 4; i++) vreg[i] = *(const float4*)(Vt + i * 4);
    };
    auto store_tile = [&](int s) {
        uint32_t base = (uint32_t)s * ATT_STG + (uint32_t)key * 144 + hb * 2;
#pragma unroll
        for (int half = 0; half < 2; half++) {
            uint4 H, L;
            split8(kreg[2 * half], kreg[2 * half + 1], H, L);
            *(uint4*)(smem + base + half * 16) = H;
            *(uint4*)(smem + 9216 + base + half * 16) = L;
            split8(vreg[2 * half], vreg[2 * half + 1], H, L);
            *(uint4*)(smem + 18432 + base + half * 16) = H;
            *(uint4*)(smem + 27648 + base + half * 16) = L;
        }
    };

    load_tile(0);
    store_tile(0);
    __syncthreads();

    const int NT = cS / 64;
    for (int kt = 0; kt < NT; kt++) {
        if (kt + 1 < NT) load_tile(kt + 1);
        uint32_t stg = sb + (kt & 1) * ATT_STG;

        float sf[8][4];
#pragma unroll
        for (int j = 0; j < 8; j++)
#pragma unroll
            for (int q = 0; q < 4; q++) sf[j][q] = 0.f;
#pragma unroll
        for (int t = 0; t < 4; t++) {
            uint32_t bk[4][4];
#pragma unroll
            for (int j = 0; j < 4; j++)
                ldmx4(bk[j], stg + (j * 16 + kb_r) * 144 + (t * 16 + kb_c) * 2);
#pragma unroll
            for (int j = 0; j < 4; j++) {
                mma16816(sf[2 * j],     qh[t], bk[j][0], bk[j][1]);
                mma16816(sf[2 * j + 1], qh[t], bk[j][2], bk[j][3]);
                mma16816(sf[2 * j],     ql[t], bk[j][0], bk[j][1]);
                mma16816(sf[2 * j + 1], ql[t], bk[j][2], bk[j][3]);
            }
#pragma unroll
            for (int j = 0; j < 4; j++)
                ldmx4(bk[j], stg + 9216 + (j * 16 + kb_r) * 144 + (t * 16 + kb_c) * 2);
#pragma unroll
            for (int j = 0; j < 4; j++) {
                mma16816(sf[2 * j],     qh[t], bk[j][0], bk[j][1]);
                mma16816(sf[2 * j + 1], qh[t], bk[j][2], bk[j][3]);
            }
        }

        float mx0 = -1e30f, mx1 = -1e30f;
#pragma unroll
        for (int j = 0; j < 8; j++) {
            mx0 = fmaxf(mx0, fmaxf(sf[j][0], sf[j][1]));
            mx1 = fmaxf(mx1, fmaxf(sf[j][2], sf[j][3]));
        }
        mx0 = fmaxf(mx0, __shfl_xor_sync(0xffffffffu, mx0, 1));
        mx0 = fmaxf(mx0, __shfl_xor_sync(0xffffffffu, mx0, 2));
        mx1 = fmaxf(mx1, __shfl_xor_sync(0xffffffffu, mx1, 1));
        mx1 = fmaxf(mx1, __shfl_xor_sync(0xffffffffu, mx1, 2));
        float mn0 = fmaxf(m0, mx0), mn1 = fmaxf(m1, mx1);
        float c0 = __expf(m0 - mn0), c1 = __expf(m1 - mn1);
        float rs0 = 0.f, rs1 = 0.f;
        uint32_t pk[4][4];
#pragma unroll
        for (int j = 0; j < 8; j++) {
            float p00 = __expf(sf[j][0] - mn0), p01 = __expf(sf[j][1] - mn0);
            float p10 = __expf(sf[j][2] - mn1), p11 = __expf(sf[j][3] - mn1);
            __nv_bfloat162 pb0 = __floats2bfloat162_rn(p00, p01);
            __nv_bfloat162 pb1 = __floats2bfloat162_rn(p10, p11);
            float2 r0 = __bfloat1622float2(pb0), r1 = __bfloat1622float2(pb1);
            rs0 += r0.x + r0.y; rs1 += r1.x + r1.y;
            pk[j >> 1][(j & 1) * 2 + 0] = bf2bits(pb0);
            pk[j >> 1][(j & 1) * 2 + 1] = bf2bits(pb1);
        }
        rs0 += __shfl_xor_sync(0xffffffffu, rs0, 1);
        rs0 += __shfl_xor_sync(0xffffffffu, rs0, 2);
        rs1 += __shfl_xor_sync(0xffffffffu, rs1, 1);
        rs1 += __shfl_xor_sync(0xffffffffu, rs1, 2);
        l0 = l0 * c0 + rs0; l1 = l1 * c1 + rs1;
#pragma unroll
        for (int j = 0; j < 8; j++) {
            of[j][0] *= c0; of[j][1] *= c0; of[j][2] *= c1; of[j][3] *= c1;
        }
        m0 = mn0; m1 = mn1;

#pragma unroll
        for (int t = 0; t < 4; t++) {
            uint32_t bv[4][4];
#pragma unroll
            for (int g = 0; g < 4; g++)
                ldmx4t(bv[g], stg + 18432 + (t * 16 + a_r) * 144 + (g * 16 + a_c) * 2);
#pragma unroll
            for (int g = 0; g < 4; g++) {
                mma16816(of[2 * g],     pk[t], bv[g][0], bv[g][1]);
                mma16816(of[2 * g + 1], pk[t], bv[g][2], bv[g][3]);
            }
#pragma unroll
            for (int g = 0; g < 4; g++)
                ldmx4t(bv[g], stg + 27648 + (t * 16 + a_r) * 144 + (g * 16 + a_c) * 2);
#pragma unroll
            for (int g = 0; g < 4; g++) {
                mma16816(of[2 * g],     pk[t], bv[g][0], bv[g][1]);
                mma16816(of[2 * g + 1], pk[t], bv[g][2], bv[g][3]);
            }
        }

        if (kt + 1 < NT) store_tile((kt + 1) & 1);
        __syncthreads();
    }

    float i0 = 1.f / l0, i1 = 1.f / l1;
    int rr = lane >> 2, cc = (lane & 3) * 2;
#pragma unroll
    for (int j = 0; j < 8; j++) {
        int col = j * 8 + cc;
        uint32_t H, L;
        __nv_bfloat16* p0 = Og + (size_t)(warp * 16 + rr) * 3072 + col;
        split2(of[j][0] * i0, of[j][1] * i0, H, L);
        *(uint32_t*)p0 = H; *(uint32_t*)(p0 + 1024) = H; *(uint32_t*)(p0 + 2048) = L;
        __nv_bfloat16* p1 = Og + (size_t)(warp * 16 + rr + 8) * 3072 + col;
        split2(of[j][2] * i1, of[j][3] * i1, H, L);
        *(uint32_t*)p1 = H; *(uint32_t*)(p1 + 1024) = H; *(uint32_t*)(p1 + 2048) = L;
    }
}

// ---------------- LayerNorm (fp32 out + fused bf16 split out) ----------------
__global__ void ln_kernel(const float* __restrict__ x, const float* __restrict__ w,
                          const float* __restrict__ b, float* __restrict__ y,
                          __nv_bfloat16* __restrict__ ys) {
    int row = blockIdx.x, t = threadIdx.x;
    float4 v = ((const float4*)(x + (size_t)row * cH))[t];
    float s1 = v.x + v.y + v.z + v.w;
    float s2 = v.x * v.x + v.y * v.y + v.z * v.z + v.w * v.w;
#pragma unroll
    for (int o = 16; o > 0; o >>= 1) {
        s1 += __shfl_xor_sync(0xffffffffu, s1, o);
        s2 += __shfl_xor_sync(0xffffffffu, s2, o);
    }
    __shared__ float sm1[8], sm2[8];
    __shared__ float s_mean, s_rstd;
    if ((t & 31) == 0) { sm1[t >> 5] = s1; sm2[t >> 5] = s2; }
    __syncthreads();
    if (t == 0) {
        float a = 0.f, c = 0.f;
#pragma unroll
        for (int i = 0; i < 8; i++) { a += sm1[i]; c += sm2[i]; }
        float mean = a * (1.0f / cH);
        float var  = c * (1.0f / cH) - mean * mean;
        s_mean = mean; s_rstd = rsqrtf(var + 1e-5f);
    }
    __syncthreads();
    float mean = s_mean, rstd = s_rstd;
    float4 wv = ((const float4*)w)[t];
    float4 bv = ((const float4*)b)[t];
    float4 o;
    o.x = (v.x - mean) * rstd * wv.x + bv.x;
    o.y = (v.y - mean) * rstd * wv.y + bv.y;
    o.z = (v.z - mean) * rstd * wv.z + bv.z;
    o.w = (v.w - mean) * rstd * wv.w + bv.w;
    ((float4*)(y + (size_t)row * cH))[t] = o;
    // fused split
    uint32_t H0, L0, H1, L1;
    split2(o.x, o.y, H0, L0);
    split2(o.z, o.w, H1, L1);
    __nv_bfloat16* yr = ys + (size_t)row * 3072 + t * 4;
    uint2 Hh; Hh.x = H0; Hh.y = H1;
    uint2 Ll; Ll.x = L0; Ll.y = L1;
    *(uint2*)yr = Hh;
    *(uint2*)(yr + 1024) = Hh;
    *(uint2*)(yr + 2048) = Ll;
}

// ---------------- small kernels ----------------
__global__ void select_kernel(const float* __restrict__ h1, float* __restrict__ h,
                              const int* __restrict__ li) {
    int L = *li;
    if ((L % 4 == 0) && L > 0) return;
    size_t i = (size_t)blockIdx.x * blockDim.x + threadIdx.x;
    ((float4*)h)[i] = ((const float4*)h1)[i];
}

__global__ void pool_kernel(const float* __restrict__ hbuf, float* __restrict__ pooled) {
    int b = blockIdx.y;
    int col = blockIdx.x * blockDim.x + threadIdx.x;
    const float* p = hbuf + (size_t)b * cS * cH + col;
    float a0 = 0, a1 = 0, a2 = 0, a3 = 0;
    for (int s = 0; s < cS; s += 4) {
        a0 += p[(size_t)s * cH];
        a1 += p[(size_t)(s + 1) * cH];
        a2 += p[(size_t)(s + 2) * cH];
        a3 += p[(size_t)(s + 3) * cH];
    }
    pooled[b * cH + col] = (a0 + a1 + a2 + a3) * (1.0f / cS);
}

__global__ void allocretr_kernel(const float* __restrict__ pooled,
                                 const float* __restrict__ aw, const float* __restrict__ ab,
                                 const float* __restrict__ rw, const float* __restrict__ rb,
                                 float* __restrict__ alloc_o, float* __restrict__ retr_o) {
    int b = blockIdx.y, which = blockIdx.x;
    const float* w  = which ? rw : aw;
    const float* bi = which ? rb : ab;
    float* out = which ? retr_o : alloc_o;
    int n = threadIdx.x;
    const float* p  = pooled + b * cH;
    const float* wr = w + (size_t)n * cH;
    float acc = bi[n];
    for (int k = 0; k < cH; k += 4)
        acc += p[k] * wr[k] + p[k + 1] * wr[k + 1] + p[k + 2] * wr[k + 2] + p[k + 3] * wr[k + 3];
    __shared__ float red[cMB];
    red[n] = acc; __syncthreads();
    for (int o = 64; o > 0; o >>= 1) { if (n < o) red[n] = fmaxf(red[n], red[n + o]); __syncthreads(); }
    float mx = red[0]; __syncthreads();
    float e = __expf(acc - mx);
    red[n] = e; __syncthreads();
    for (int o = 64; o > 0; o >>= 1) { if (n < o) red[n] += red[n + o]; __syncthreads(); }
    out[b * cMB + n] = e / red[0];
}

__global__ void retrieve_kernel(const float* __restrict__ retr_o,
                                const float* __restrict__ memb, float* __restrict__ retrv) {
    int b = blockIdx.y;
    int col = blockIdx.x * blockDim.x + threadIdx.x;
    float acc = 0.f;
#pragma unroll 4
    for (int r = 0; r < cMB; r++) acc += retr_o[b * cMB + r] * memb[(size_t)r * cH + col];
    retrv[b * cH + col] = acc;
}

// h += scale*retrieved; also emit bf16 split of the result (self-attn GEMM input)
__global__ void addmem_kernel(float* __restrict__ h, const float* __restrict__ retrv,
                              const float* __restrict__ msc, const int* __restrict__ li,
                              __nv_bfloat16* __restrict__ hs) {
    float sc = msc[*li];
    size_t idx = ((size_t)blockIdx.x * blockDim.x + threadIdx.x) * 4;
    size_t row = idx / cH;
    int b = (int)(row / cS);
    int c = (int)(idx % cH);
    float4 r = *(const float4*)(retrv + b * cH + c);
    float4 v = *(float4*)(h + idx);
    v.x += r.x * sc; v.y += r.y * sc; v.z += r.z * sc; v.w += r.w * sc;
    *(float4*)(h + idx) = v;
    uint32_t H0, L0, H1, L1;
    split2(v.x, v.y, H0, L0);
    split2(v.z, v.w, H1, L1);
    __nv_bfloat16* yr = hs + row * 3072 + c;
    uint2 Hh; Hh.x = H0; Hh.y = H1;
    uint2 Ll; Ll.x = L0; Ll.y = L1;
    *(uint2*)yr = Hh;
    *(uint2*)(yr + 1024) = Hh;
    *(uint2*)(yr + 2048) = Ll;
}

__global__ void pooled2_kernel(const float* __restrict__ pooled, const float* __restrict__ retrv,
                               const float* __restrict__ msc, const int* __restrict__ li,
                               float* __restrict__ pooled2) {
    float sc = msc[*li];
    int i = blockIdx.x * blockDim.x + threadIdx.x;
    pooled2[i] = pooled[i] + retrv[i] * sc;
}

__global__ void upd_kernel(const float* __restrict__ pooled2, const float* __restrict__ uw,
                           const float* __restrict__ ub, float* __restrict__ sig) {
    int b = blockIdx.y;
    int n = blockIdx.x * blockDim.x + threadIdx.x;
    const float* p = pooled2 + b * cH;
    const float* w = uw + (size_t)n * cH;
    float acc = ub[n];
    for (int k = 0; k < cH; k += 4)
        acc += p[k] * w[k] + p[k + 1] * w[k + 1] + p[k + 2] * w[k + 2] + p[k + 3] * w[k + 3];
    sig[b * cH + n] = 1.f / (1.f + __expf(-acc));
}

__global__ void topk_kernel(const float* __restrict__ alloc_o, int* __restrict__ top) {
    int b = blockIdx.x;
    if (threadIdx.x != 0) return;
    float v[cMB];
    for (int i = 0; i < cMB; i++) v[i] = alloc_o[b * cMB + i];
    for (int k = 0; k < cTOPK; k++) {
        int arg = 0; float best = v[0];
        for (int i = 1; i < cMB; i++) if (v[i] > best) { best = v[i]; arg = i; }
        top[b * cTOPK + k] = arg;
        v[arg] = -1e30f;
    }
}

__global__ void scatter_kernel(const int* __restrict__ top, const float* __restrict__ sig,
                               const float* __restrict__ memb, float* __restrict__ outm) {
    int r = blockIdx.x;
    __shared__ int sel;
    if (threadIdx.x == 0) {
        int s = -1;
        for (int bb = 0; bb < cB; bb++)
            for (int k = 0; k < cTOPK; k++)
                if (top[bb * cTOPK + k] == r) s = bb;
        sel = s;
    }
    __syncthreads();
    const float* src = (sel >= 0) ? (sig + (size_t)sel * cH) : (memb + (size_t)r * cH);
    for (int c = threadIdx.x; c < cH; c += blockDim.x)
        outm[(size_t)r * cH + c] = src[c];
}

// ---------------- launch ----------------
extern "C" void kernel_launch(void* const* d_in, const int* in_sizes, int n_in,
                              void* d_out, int out_size) {
    (void)in_sizes; (void)n_in; (void)out_size;
    const float* x    = (const float*)d_in[0];
    const float* ln1w = (const float*)d_in[1];
    const float* ln1b = (const float*)d_in[2];
    const float* ln2w = (const float*)d_in[3];
    const float* ln2b = (const float*)d_in[4];
    const float* wq   = (const float*)d_in[5];
    const float* wk   = (const float*)d_in[6];
    const float* wv   = (const float*)d_in[7];
    const float* wo   = (const float*)d_in[8];
    const float* ad1  = (const float*)d_in[9];
    const float* ad2  = (const float*)d_in[10];
    const float* memb = (const float*)d_in[11];
    const float* aw   = (const float*)d_in[12];
    const float* ab   = (const float*)d_in[13];
    const float* rw   = (const float*)d_in[14];
    const float* rb   = (const float*)d_in[15];
    const float* uw   = (const float*)d_in[16];
    const float* ub   = (const float*)d_in[17];
    const float* msc  = (const float*)d_in[18];
    const float* aiw  = (const float*)d_in[19];
    const float* aib  = (const float*)d_in[20];
    const float* aow  = (const float*)d_in[21];
    const float* aob  = (const float*)d_in[22];
    const float* m1w  = (const float*)d_in[23];
    const float* m1b  = (const float*)d_in[24];
    const float* m2w  = (const float*)d_in[25];
    const float* m2b  = (const float*)d_in[26];
    const int*   li   = (const int*)d_in[27];
    float* out  = (float*)d_out;
    float* outm = out + (size_t)cM * cH;

    float *p_h1, *p_h, *p_h4, *p_qkv;
    float *p_pooled, *p_pooled2, *p_alloc, *p_retr, *p_retrv, *p_sig;
    int* p_top;
    __nv_bfloat16 *p_sA, *p_sF, *p_sW;
    cudaGetSymbolAddress((void**)&p_h1, g_h1);
    cudaGetSymbolAddress((void**)&p_h, g_h);
    cudaGetSymbolAddress((void**)&p_h4, g_h4);
    cudaGetSymbolAddress((void**)&p_qkv, g_qkv);
    cudaGetSymbolAddress((void**)&p_pooled, g_pooled);
    cudaGetSymbolAddress((void**)&p_pooled2, g_pooled2);
    cudaGetSymbolAddress((void**)&p_alloc, g_allocp);
    cudaGetSymbolAddress((void**)&p_retr, g_retrp);
    cudaGetSymbolAddress((void**)&p_retrv, g_retrv);
    cudaGetSymbolAddress((void**)&p_sig, g_sig);
    cudaGetSymbolAddress((void**)&p_top, g_top);
    cudaGetSymbolAddress((void**)&p_sA, g_sA);
    cudaGetSymbolAddress((void**)&p_sF, g_sF);
    cudaGetSymbolAddress((void**)&p_sW, g_sW);
    __nv_bfloat16* p_sB = p_sF;   // t1 split ping-pong buffer (dead before MLP uses sF)

    const int GSM = GSTAGES * GSTG_B;   // 110592
    cudaFuncSetAttribute(mma_gemm_kernel, cudaFuncAttributeMaxDynamicSharedMemorySize, GSM);
    const int ASM = 2 * ATT_STG;        // 73728
    cudaFuncSetAttribute(attn_mma_kernel, cudaFuncAttributeMaxDynamicSharedMemorySize, ASM);

    dim3 gattn(cS / 128, cNH, cB);
    auto splitW = [&](const float* src, __nv_bfloat16* dst, int N, int K) {
        split_kernel<<<(int)(((size_t)N * K / 4) / 256), 256>>>(src, dst, K, 1);
    };

    ln_kernel<<<cM, 256>>>(x, ln1w, ln1b, p_h1, p_sA);
    // --- recycle branch (layer_idx=4 active; select_kernel handles the other case) ---
    splitW(wq, p_sW,                          cH, cH);
    splitW(wk, p_sW + (size_t)1024 * 3072,    cH, cH);
    splitW(wv, p_sW + (size_t)2048 * 3072,    cH, cH);
    mma_gemm_kernel<<<dim3(24, 64), 256, GSM>>>(p_sA, p_sW, 3072, p_qkv, 3 * cH, nullptr, 0, nullptr, nullptr, 0, 0);
    attn_mma_kernel<<<gattn, 256, ASM>>>(p_qkv, p_qkv + cH, p_qkv + 2 * cH, 3 * cH, p_sA);
    splitW(wo, p_sW, cH, cH);
    mma_gemm_kernel<<<dim3(8, 64), 256, GSM>>>(p_sA, p_sW, 3072, nullptr, 0, p_sB, cH, nullptr, nullptr, 0, 0);
    splitW(ad1, p_sW, cH / 4, cH);
    mma_gemm_kernel<<<dim3(2, 64), 256, GSM>>>(p_sB, p_sW, 3072, nullptr, 0, p_sA, cH / 4, nullptr, nullptr, 0, 1);
    splitW(ad2, p_sW, cH, cH / 4);
    mma_gemm_kernel<<<dim3(8, 64), 256, GSM>>>(p_sA, p_sW, 768, p_h, cH, nullptr, 0, nullptr, nullptr, 0, 0);
    select_kernel<<<cM * cH / 4 / 256, 256>>>(p_h1, p_h, li);
    // --- memory manager ---
    pool_kernel<<<dim3(cH / 256, cB), 256>>>(p_h, p_pooled);
    allocretr_kernel<<<dim3(2, cB), cMB>>>(p_pooled, aw, ab, rw, rb, p_alloc, p_retr);
    retrieve_kernel<<<dim3(cH / 256, cB), 256>>>(p_retr, memb, p_retrv);
    addmem_kernel<<<cM * cH / 4 / 256, 256>>>(p_h, p_retrv, msc, li, p_sA);
    pooled2_kernel<<<cB * cH / 256, 256>>>(p_pooled, p_retrv, msc, li, p_pooled2);
    upd_kernel<<<dim3(cH / 128, cB), 128>>>(p_pooled2, uw, ub, p_sig);
    topk_kernel<<<cB, 32>>>(p_alloc, p_top);
    scatter_kernel<<<cMB, 256>>>(p_top, p_sig, memb, outm);
    // --- self attention ---
    splitW(aiw, p_sW, 3 * cH, cH);
    mma_gemm_kernel<<<dim3(24, 64), 256, GSM>>>(p_sA, p_sW, 3072, p_qkv, 3 * cH, nullptr, 0, aib, nullptr, 0, 0);
    attn_mma_kernel<<<gattn, 256, ASM>>>(p_qkv, p_qkv + cH, p_qkv + 2 * cH, 3 * cH, p_sA);
    splitW(aow, p_sW, cH, cH);
    mma_gemm_kernel<<<dim3(8, 64), 256, GSM>>>(p_sA, p_sW, 3072, p_h4, cH, nullptr, 0, aob, x, cH, 0);
    // --- MLP ---
    ln_kernel<<<cM, 256>>>(p_h4, ln2w, ln2b, p_h1, p_sA);
    splitW(m1w, p_sW, cFF, cH);
    mma_gemm_kernel<<<dim3(32, 64), 256, GSM>>>(p_sA, p_sW, 3072, nullptr, 0, p_sF, cFF, m1b, nullptr, 0, 2);
    splitW(m2w, p_sW, cH, cFF);
    mma_gemm_kernel<<<dim3(8, 64), 256, GSM>>>(p_sF, p_sW, 12288, out, cH, nullptr, 0, m2b, p_h4, cH, 0);
}